// round 4
// baseline (speedup 1.0000x reference)
#include <cuda_runtime.h>
#include <math.h>

#define QLEN 1024
#define BATCH 4
#define DMODEL 512
#define HEADS 8
#define DHEAD 64
#define MEMLEN 1024
#define KLEN 2048
#define DMLP 2048
#define BH 32
#define QROWS 4096
#define KROWS 8192
#define QKVW 1536
#define QSTRIDE 6144
#define QK ((size_t)QLEN * KLEN)

// ---------------- scratch ----------------
__device__ float g_qkv[KROWS * QKVW];
__device__ float g_rk[KLEN * DMODEL];
__device__ float g_qu[BH * QLEN * DHEAD];
__device__ float g_qv[BH * QLEN * DHEAD];
__device__ float g_vt[BH * DHEAD * KLEN];
__device__ float g_S[(size_t)BH * QLEN * KLEN];
__device__ float g_BD[(size_t)BH * QLEN * KLEN];
__device__ float2 g_stat[BH * QLEN];
__device__ float g_attn[QROWS * DMODEL];
__device__ float g_ao[QROWS * DMODEL];
__device__ float g_y[QROWS * DMODEL];
__device__ float g_yr[QROWS * DMODEL];
__device__ float g_h[QROWS * DMLP];
__device__ float g_z[QROWS * DMODEL];
// RNA-rounded copies of inputs/weights (tf32-safe operands)
__device__ float g_memr[MEMLEN * BATCH * DMODEL];
__device__ float g_inr[QLEN * BATCH * DMODEL];
__device__ float g_rr[KLEN * DMODEL];
__device__ float g_wqkv[QKVW * DMODEL];
__device__ float g_wr[DMODEL * DMODEL];
__device__ float g_wo[DMODEL * DMODEL];
__device__ float g_w1[DMLP * DMODEL];
__device__ float g_w2[DMODEL * DMLP];

// ---------------- helpers ----------------
__device__ __forceinline__ float f2tf(float x) {
    unsigned r;
    asm("cvt.rna.tf32.f32 %0, %1;" : "=r"(r) : "f"(x));
    return __uint_as_float(r);
}
__device__ __forceinline__ void cp16(float* dst_smem, const float* src) {
    unsigned d = (unsigned)__cvta_generic_to_shared(dst_smem);
    asm volatile("cp.async.ca.shared.global [%0], [%1], 16;" :: "r"(d), "l"(src));
}
__device__ __forceinline__ void cp_commit() { asm volatile("cp.async.commit_group;"); }
__device__ __forceinline__ void cp_wait1()  { asm volatile("cp.async.wait_group 1;"); }
__device__ __forceinline__ void cp_wait0()  { asm volatile("cp.async.wait_group 0;"); }

__device__ __forceinline__ void mma_tf32(float* acc, unsigned a0, unsigned a1,
                                         unsigned a2, unsigned a3,
                                         unsigned b0, unsigned b1) {
    asm volatile(
        "mma.sync.aligned.m16n8k8.row.col.f32.tf32.tf32.f32 "
        "{%0,%1,%2,%3}, {%4,%5,%6,%7}, {%8,%9}, {%0,%1,%2,%3};"
        : "+f"(acc[0]), "+f"(acc[1]), "+f"(acc[2]), "+f"(acc[3])
        : "r"(a0), "r"(a1), "r"(a2), "r"(a3), "r"(b0), "r"(b1));
}

// ---------------- RNA round-copy ----------------
__global__ void round_copy(const float* __restrict__ src, float* __restrict__ dst,
                           int n4) {
    int idx = blockIdx.x * blockDim.x + threadIdx.x;
    if (idx < n4) {
        float4 v = ((const float4*)src)[idx];
        v.x = f2tf(v.x); v.y = f2tf(v.y); v.z = f2tf(v.z); v.w = f2tf(v.w);
        ((float4*)dst)[idx] = v;
    }
}

// ---------------- tf32 NT GEMM core: acc += A[BM,K]@B[BN,K]^T ----------------
template<int BM, int BN, int WM, int WN, int NTH>
__device__ __forceinline__ void gemm_core(
    const float* __restrict__ A, int lda,
    const float* __restrict__ B, int ldb,
    int K0, int K1, float acc[WM/16][WN/8][4])
{
    constexpr int WARPS_M = BM / WM;
    constexpr int MT = WM / 16;
    constexpr int NT = WN / 8;
    constexpr int LA = (BM * 4) / NTH;
    constexpr int LB = (BN * 4) / NTH;
    __shared__ float As[2][BM][20];
    __shared__ float Bs[2][BN][20];
    const int tid = threadIdx.x;
    const int lane = tid & 31;
    const int warp = tid >> 5;
    const int wm = warp % WARPS_M;
    const int wn = warp / WARPS_M;
    const int grp = lane >> 2, tig = lane & 3;

    #pragma unroll
    for (int mt = 0; mt < MT; mt++)
        #pragma unroll
        for (int nt = 0; nt < NT; nt++)
            #pragma unroll
            for (int q = 0; q < 4; q++) acc[mt][nt][q] = 0.0f;

    const int nk = (K1 - K0) >> 4;
    #pragma unroll
    for (int l = 0; l < LA; l++) {
        int idx = l * NTH + tid;
        int r = idx >> 2, c4 = (idx & 3) << 2;
        cp16(&As[0][r][c4], A + (size_t)r * lda + K0 + c4);
    }
    #pragma unroll
    for (int l = 0; l < LB; l++) {
        int idx = l * NTH + tid;
        int r = idx >> 2, c4 = (idx & 3) << 2;
        cp16(&Bs[0][r][c4], B + (size_t)r * ldb + K0 + c4);
    }
    cp_commit();

    int cur = 0;
    for (int it = 0; it < nk; it++) {
        if (it + 1 < nk) {
            int kt = K0 + (it + 1) * 16;
            #pragma unroll
            for (int l = 0; l < LA; l++) {
                int idx = l * NTH + tid;
                int r = idx >> 2, c4 = (idx & 3) << 2;
                cp16(&As[cur ^ 1][r][c4], A + (size_t)r * lda + kt + c4);
            }
            #pragma unroll
            for (int l = 0; l < LB; l++) {
                int idx = l * NTH + tid;
                int r = idx >> 2, c4 = (idx & 3) << 2;
                cp16(&Bs[cur ^ 1][r][c4], B + (size_t)r * ldb + kt + c4);
            }
            cp_commit();
            cp_wait1();
        } else {
            cp_wait0();
        }
        __syncthreads();
        #pragma unroll
        for (int ks = 0; ks < 16; ks += 8) {
            unsigned af[MT][4], bf[NT][2];
            #pragma unroll
            for (int mt = 0; mt < MT; mt++) {
                int rowb = wm * WM + mt * 16;
                af[mt][0] = __float_as_uint(As[cur][rowb + grp][ks + tig]);
                af[mt][1] = __float_as_uint(As[cur][rowb + grp + 8][ks + tig]);
                af[mt][2] = __float_as_uint(As[cur][rowb + grp][ks + tig + 4]);
                af[mt][3] = __float_as_uint(As[cur][rowb + grp + 8][ks + tig + 4]);
            }
            #pragma unroll
            for (int nt = 0; nt < NT; nt++) {
                int colb = wn * WN + nt * 8 + grp;
                bf[nt][0] = __float_as_uint(Bs[cur][colb][ks + tig]);
                bf[nt][1] = __float_as_uint(Bs[cur][colb][ks + tig + 4]);
            }
            #pragma unroll
            for (int mt = 0; mt < MT; mt++)
                #pragma unroll
                for (int nt = 0; nt < NT; nt++)
                    mma_tf32(acc[mt][nt], af[mt][0], af[mt][1], af[mt][2], af[mt][3],
                             bf[nt][0], bf[nt][1]);
        }
        __syncthreads();
        cur ^= 1;
    }
}

// ---------------- linear GEMM (act: +1 bias, +2 relu, +4 round-out) ----------
__global__ __launch_bounds__(256, 2) void lin_gemm(
    const float* __restrict__ A, const float* __restrict__ W,
    const float* __restrict__ bias, float* __restrict__ C,
    int K, int N, int act)
{
    int m0 = blockIdx.y * 128, n0 = blockIdx.x * 128;
    float acc[2][8][4];
    gemm_core<128, 128, 32, 64, 256>(A + (size_t)m0 * K, K,
                                     W + (size_t)n0 * K, K, 0, K, acc);
    const int lane = threadIdx.x & 31, warp = threadIdx.x >> 5;
    const int wm = warp % 4, wn = warp / 4;
    const int grp = lane >> 2, tig = lane & 3;
    float* Cp = C + (size_t)m0 * N + n0;
    const float* bp = bias ? bias + n0 : nullptr;
    #pragma unroll
    for (int mt = 0; mt < 2; mt++) {
        int r0 = wm * 32 + mt * 16 + grp;
        #pragma unroll
        for (int nt = 0; nt < 8; nt++) {
            int c0 = wn * 64 + nt * 8 + tig * 2;
            float v0 = acc[mt][nt][0], v1 = acc[mt][nt][1];
            float v2 = acc[mt][nt][2], v3 = acc[mt][nt][3];
            if (act & 1) {
                float b0 = bp[c0], b1 = bp[c0 + 1];
                v0 += b0; v1 += b1; v2 += b0; v3 += b1;
            }
            if (act & 2) {
                v0 = fmaxf(v0, 0.f); v1 = fmaxf(v1, 0.f);
                v2 = fmaxf(v2, 0.f); v3 = fmaxf(v3, 0.f);
            }
            if (act & 4) {
                v0 = f2tf(v0); v1 = f2tf(v1); v2 = f2tf(v2); v3 = f2tf(v3);
            }
            *(float2*)(Cp + (size_t)r0 * N + c0) = make_float2(v0, v1);
            *(float2*)(Cp + (size_t)(r0 + 8) * N + c0) = make_float2(v2, v3);
        }
    }
}

// ---------------- BD raw scores (position term) -------------------------------
__global__ __launch_bounds__(256, 2) void score_bd(
    const float* __restrict__ Qv, const float* __restrict__ rk,
    float* __restrict__ BD)
{
    int bh = blockIdx.z, h = bh & 7;
    int i0 = blockIdx.y * 128, p0 = blockIdx.x * 128;
    if (p0 + i0 < 896) return;
    float acc[2][8][4];
    gemm_core<128, 128, 32, 64, 256>(Qv + ((size_t)bh * QLEN + i0) * DHEAD, DHEAD,
                                     rk + (size_t)p0 * DMODEL + h * DHEAD, DMODEL,
                                     0, DHEAD, acc);
    const int lane = threadIdx.x & 31, warp = threadIdx.x >> 5;
    const int wm = warp % 4, wn = warp / 4;
    const int grp = lane >> 2, tig = lane & 3;
    float* Cp = BD + (size_t)bh * QK + (size_t)i0 * KLEN + p0;
    #pragma unroll
    for (int mt = 0; mt < 2; mt++) {
        int r0 = wm * 32 + mt * 16 + grp;
        #pragma unroll
        for (int nt = 0; nt < 8; nt++) {
            int c0 = wn * 64 + nt * 8 + tig * 2;
            *(float2*)(Cp + (size_t)r0 * KLEN + c0) =
                make_float2(acc[mt][nt][0], acc[mt][nt][1]);
            *(float2*)(Cp + (size_t)(r0 + 8) * KLEN + c0) =
                make_float2(acc[mt][nt][2], acc[mt][nt][3]);
        }
    }
}

// ---------------- AC scores fused with BD rel-shift add + scale --------------
__global__ __launch_bounds__(256, 2) void score_ac(
    const float* __restrict__ Qu, const float* __restrict__ qkv,
    const float* __restrict__ BD, float* __restrict__ S)
{
    int bh = blockIdx.z, b = bh >> 3, h = bh & 7;
    int i0 = blockIdx.y * 128, j0 = blockIdx.x * 128;
    if (j0 - i0 > 1024) return;
    float acc[2][8][4];
    gemm_core<128, 128, 32, 64, 256>(
        Qu + ((size_t)bh * QLEN + i0) * DHEAD, DHEAD,
        qkv + (size_t)j0 * QSTRIDE + b * QKVW + DMODEL + h * DHEAD, QSTRIDE,
        0, DHEAD, acc);
    const int lane = threadIdx.x & 31, warp = threadIdx.x >> 5;
    const int wm = warp % 4, wn = warp / 4;
    const int grp = lane >> 2, tig = lane & 3;
    const float* bdb = BD + (size_t)bh * QK;
    float* Sp = S + (size_t)bh * QK;
    #pragma unroll
    for (int mt = 0; mt < 2; mt++) {
        #pragma unroll
        for (int hh = 0; hh < 2; hh++) {
            int gi = i0 + wm * 32 + mt * 16 + grp + hh * 8;
            const float* bdr = bdb + (size_t)gi * KLEN;
            #pragma unroll
            for (int nt = 0; nt < 8; nt++) {
                int gj = j0 + wn * 64 + nt * 8 + tig * 2;
                int p0 = min(gj - gi + (QLEN - 1), KLEN - 1);
                int p1 = min(gj + 1 - gi + (QLEN - 1), KLEN - 1);
                float v0 = (acc[mt][nt][hh * 2 + 0] + bdr[p0]) * 0.125f;
                float v1 = (acc[mt][nt][hh * 2 + 1] + bdr[p1]) * 0.125f;
                *(float2*)(Sp + (size_t)gi * KLEN + gj) = make_float2(v0, v1);
            }
        }
    }
}

// ---------------- rowstat: per (bh,i) max & inv-sum of exp --------------------
__global__ void rowstat(const float* __restrict__ S, float2* __restrict__ stat) {
    const int i = blockIdx.x, bh = blockIdx.y, tid = threadIdx.x;
    __shared__ float red[256];
    const float* row = S + (size_t)bh * QK + (size_t)i * KLEN;
    const int n = i + MEMLEN + 1;
    float m = -1e30f;
    for (int j = tid; j < n; j += 256) m = fmaxf(m, row[j]);
    red[tid] = m; __syncthreads();
    for (int o = 128; o > 0; o >>= 1) {
        if (tid < o) red[tid] = fmaxf(red[tid], red[tid + o]);
        __syncthreads();
    }
    m = red[0]; __syncthreads();
    float s = 0.f;
    for (int j = tid; j < n; j += 256) s += __expf(row[j] - m);
    red[tid] = s; __syncthreads();
    for (int o = 128; o > 0; o >>= 1) {
        if (tid < o) red[tid] += red[tid + o];
        __syncthreads();
    }
    if (tid == 0) stat[bh * QLEN + i] = make_float2(m, 1.0f / red[0]);
}

// ---------------- prob output: exp+normalize+transpose -> d_out[i,j,bh] ------
__global__ void probout(const float* __restrict__ S, const float2* __restrict__ stat,
                        float* __restrict__ out) {
    __shared__ float t[32][33];
    __shared__ float m_s[32], inv_s[32];
    const int i = blockIdx.y, j0 = blockIdx.x * 32;
    const int tid = threadIdx.x;
    if (tid < 32) {
        float2 st = stat[tid * QLEN + i];
        m_s[tid] = st.x; inv_s[tid] = st.y;
    }
    __syncthreads();
    const int lj = tid & 31, lb = tid >> 5;
    const int jmax = i + MEMLEN;
    #pragma unroll
    for (int r = 0; r < 4; r++) {
        int bh = r * 8 + lb;
        int j = j0 + lj;
        float val = 0.0f;
        if (j <= jmax)
            val = __expf(S[((size_t)bh * QLEN + i) * KLEN + j] - m_s[bh]) * inv_s[bh];
        t[lj][bh] = val;
    }
    __syncthreads();
    const int lbh = tid & 31, ljw = tid >> 5;
    #pragma unroll
    for (int r = 0; r < 4; r++) {
        int jj = r * 8 + ljw;
        out[((size_t)i * KLEN + j0 + jj) * 32 + lbh] = t[jj][lbh];
    }
}

// ---------------- attention: exp(S) on the fly @ Vt, normalize in epilogue ----
__global__ __launch_bounds__(128) void attn_exp_gemm(
    const float* __restrict__ S, const float2* __restrict__ stat,
    const float* __restrict__ Vt, float* __restrict__ attn)
{
    const int bh = blockIdx.y, b = bh >> 3, h = bh & 7;
    const int i0 = blockIdx.x * 64;
    __shared__ float As[64][20];
    __shared__ float Bs[2][64][20];
    __shared__ float m_s[64], inv_s[64];
    const int tid = threadIdx.x;
    const int lane = tid & 31, warp = tid >> 5;
    const int wm = warp & 1, wn = warp >> 1;
    const int grp = lane >> 2, tig = lane & 3;
    if (tid < 64) {
        float2 st = stat[bh * QLEN + i0 + tid];
        m_s[tid] = st.x; inv_s[tid] = st.y;
    }
    __syncthreads();

    const float* Srow = S + (size_t)bh * QK + (size_t)i0 * KLEN;
    const float* Vb = Vt + (size_t)bh * DHEAD * KLEN;
    const int K1 = min(KLEN, i0 + 64 + MEMLEN);
    const int nk = K1 >> 4;

    float acc[2][4][4];
    #pragma unroll
    for (int mt = 0; mt < 2; mt++)
        #pragma unroll
        for (int nt = 0; nt < 4; nt++)
            #pragma unroll
            for (int q = 0; q < 4; q++) acc[mt][nt][q] = 0.f;

    // prefetch
    float4 aReg[2];
    #pragma unroll
    for (int l = 0; l < 2; l++) {
        int idx = l * 128 + tid;
        int r = idx >> 2, c4 = (idx & 3) << 2;
        aReg[l] = *(const float4*)(Srow + (size_t)r * KLEN + c4);
    }
    #pragma unroll
    for (int l = 0; l < 2; l++) {
        int idx = l * 128 + tid;
        int r = idx >> 2, c4 = (idx & 3) << 2;
        cp16(&Bs[0][r][c4], Vb + (size_t)r * KLEN + c4);
    }
    cp_commit();

    int cur = 0;
    for (int it = 0; it < nk; it++) {
        const int kt = it * 16;
        float4 aNext[2];
        if (it + 1 < nk) {
            int ktn = kt + 16;
            #pragma unroll
            for (int l = 0; l < 2; l++) {
                int idx = l * 128 + tid;
                int r = idx >> 2, c4 = (idx & 3) << 2;
                cp16(&Bs[cur ^ 1][r][c4], Vb + (size_t)r * KLEN + ktn + c4);
                aNext[l] = *(const float4*)(Srow + (size_t)r * KLEN + ktn + c4);
            }
            cp_commit();
        }
        // exp + round + STS A (prev iter's trailing sync protects As)
        #pragma unroll
        for (int l = 0; l < 2; l++) {
            int idx = l * 128 + tid;
            int r = idx >> 2, c4 = (idx & 3) << 2;
            float mr = m_s[r];
            int jmax = i0 + r + MEMLEN;
            float e0 = (kt + c4 + 0 <= jmax) ? f2tf(__expf(aReg[l].x - mr)) : 0.f;
            float e1 = (kt + c4 + 1 <= jmax) ? f2tf(__expf(aReg[l].y - mr)) : 0.f;
            float e2 = (kt + c4 + 2 <= jmax) ? f2tf(__expf(aReg[l].z - mr)) : 0.f;
            float e3 = (kt + c4 + 3 <= jmax) ? f2tf(__expf(aReg[l].w - mr)) : 0.f;
            As[r][c4]     = e0;
            As[r][c4 + 1] = e1;
            As[r][c4 + 2] = e2;
            As[r][c4 + 3] = e3;
        }
        if (it + 1 < nk) cp_wait1(); else cp_wait0();
        __syncthreads();
        #pragma unroll
        for (int ks = 0; ks < 16; ks += 8) {
            unsigned af[2][4], bf[4][2];
            #pragma unroll
            for (int mt = 0; mt < 2; mt++) {
                int rowb = wm * 32 + mt * 16;
                af[mt][0] = __float_as_uint(As[rowb + grp][ks + tig]);
                af[mt][1] = __float_as_uint(As[rowb + grp + 8][ks + tig]);
                af[mt][2] = __float_as_uint(As[rowb + grp][ks + tig + 4]);
                af[mt][3] = __float_as_uint(As[rowb + grp + 8][ks + tig + 4]);
            }
            #pragma unroll
            for (int nt = 0; nt < 4; nt++) {
                int colb = wn * 32 + nt * 8 + grp;
                bf[nt][0] = __float_as_uint(Bs[cur][colb][ks + tig]);
                bf[nt][1] = __float_as_uint(Bs[cur][colb][ks + tig + 4]);
            }
            #pragma unroll
            for (int mt = 0; mt < 2; mt++)
                #pragma unroll
                for (int nt = 0; nt < 4; nt++)
                    mma_tf32(acc[mt][nt], af[mt][0], af[mt][1], af[mt][2], af[mt][3],
                             bf[nt][0], bf[nt][1]);
        }
        __syncthreads();
        aReg[0] = aNext[0]; aReg[1] = aNext[1];
        cur ^= 1;
    }

    #pragma unroll
    for (int mt = 0; mt < 2; mt++) {
        int r0 = wm * 32 + mt * 16 + grp;
        float iv0 = inv_s[r0], iv1 = inv_s[r0 + 8];
        #pragma unroll
        for (int nt = 0; nt < 4; nt++) {
            int c0 = wn * 32 + nt * 8 + tig * 2;
            float v0 = f2tf(acc[mt][nt][0] * iv0);
            float v1 = f2tf(acc[mt][nt][1] * iv0);
            float v2 = f2tf(acc[mt][nt][2] * iv1);
            float v3 = f2tf(acc[mt][nt][3] * iv1);
            size_t o0 = ((size_t)(i0 + r0) * BATCH + b) * DMODEL + h * DHEAD + c0;
            size_t o1 = ((size_t)(i0 + r0 + 8) * BATCH + b) * DMODEL + h * DHEAD + c0;
            *(float2*)(attn + o0) = make_float2(v0, v1);
            *(float2*)(attn + o1) = make_float2(v2, v3);
        }
    }
}

// ---------------- prep: Qu/Qv (rounded) ----------------
__global__ void prep_quv(const float* __restrict__ qkv, const float* __restrict__ u,
                         const float* __restrict__ v, float* __restrict__ Qu,
                         float* __restrict__ Qv) {
    int i = blockIdx.x, b = blockIdx.y, t = threadIdx.x;
    float q = qkv[(size_t)(MEMLEN + i) * QSTRIDE + b * QKVW + t];
    int h = t >> 6, d = t & 63;
    size_t o = ((size_t)(b * HEADS + h) * QLEN + i) * DHEAD + d;
    Qu[o] = f2tf(q + u[t]);
    Qv[o] = f2tf(q + v[t]);
}

// ---------------- prep: Vt[bh][d][j] ----------------
__global__ void prep_vt(const float* __restrict__ qkv, float* __restrict__ Vt) {
    __shared__ float t[32][33];
    int bh = blockIdx.z, b = bh >> 3, h = bh & 7;
    int j0 = blockIdx.x * 32, d0 = blockIdx.y * 32;
    int tc = threadIdx.x & 31, tr = threadIdx.x >> 5;
    #pragma unroll
    for (int rr = 0; rr < 32; rr += 8)
        t[tr + rr][tc] = qkv[(size_t)(j0 + tr + rr) * QSTRIDE + b * QKVW
                             + 2 * DMODEL + h * DHEAD + d0 + tc];
    __syncthreads();
    #pragma unroll
    for (int rr = 0; rr < 32; rr += 8)
        Vt[((size_t)bh * DHEAD + d0 + tr + rr) * KLEN + j0 + tc] = t[tc][tr + rr];
}

// ---------------- residual add + layernorm (optional rounded copy) -----------
__global__ void add_ln(const float* __restrict__ x1, const float* __restrict__ x2,
                       const float* __restrict__ g, const float* __restrict__ bb,
                       float* __restrict__ out, float* __restrict__ out_r) {
    const int row = blockIdx.x;
    const int tid = threadIdx.x;
    __shared__ float red[256];
    __shared__ float red2[256];
    const float* a = x1 + (size_t)row * DMODEL;
    const float* c = x2 + (size_t)row * DMODEL;
    float v0 = a[tid] + c[tid];
    float v1 = a[tid + 256] + c[tid + 256];
    red[tid] = v0 + v1;
    red2[tid] = v0 * v0 + v1 * v1;
    __syncthreads();
    for (int o = 128; o > 0; o >>= 1) {
        if (tid < o) { red[tid] += red[tid + o]; red2[tid] += red2[tid + o]; }
        __syncthreads();
    }
    const float mu = red[0] * (1.0f / DMODEL);
    const float var = red2[0] * (1.0f / DMODEL) - mu * mu;
    const float rstd = rsqrtf(var + 1e-5f);
    float* o = out + (size_t)row * DMODEL;
    float r0 = (v0 - mu) * rstd * g[tid] + bb[tid];
    float r1 = (v1 - mu) * rstd * g[tid + 256] + bb[tid + 256];
    o[tid] = r0;
    o[tid + 256] = r1;
    if (out_r) {
        float* orr = out_r + (size_t)row * DMODEL;
        orr[tid] = f2tf(r0);
        orr[tid + 256] = f2tf(r1);
    }
}

// ---------------- launch ----------------
extern "C" void kernel_launch(void* const* d_in, const int* in_sizes, int n_in,
                              void* d_out, int out_size) {
    const float* inputs = (const float*)d_in[0];
    const float* r      = (const float*)d_in[1];
    const float* u      = (const float*)d_in[2];
    const float* v      = (const float*)d_in[3];
    const float* mem    = (const float*)d_in[4];
    const float* Wqkv   = (const float*)d_in[6];
    const float* Wr     = (const float*)d_in[7];
    const float* Wo     = (const float*)d_in[8];
    const float* ln1_g  = (const float*)d_in[9];
    const float* ln1_b  = (const float*)d_in[10];
    const float* w1     = (const float*)d_in[11];
    const float* b1     = (const float*)d_in[12];
    const float* w2     = (const float*)d_in[13];
    const float* b2     = (const float*)d_in[14];
    const float* ln2_g  = (const float*)d_in[15];
    const float* ln2_b  = (const float*)d_in[16];

    float *qkvp, *rkp, *qup, *qvp, *vtp, *sp, *bdp, *attnp, *aop, *yp, *yrp, *hp, *zp;
    float *memr, *inr, *rr, *wqkvr, *wrr, *wor, *w1r, *w2r;
    float2* statp;
    cudaGetSymbolAddress((void**)&qkvp,  g_qkv);
    cudaGetSymbolAddress((void**)&rkp,   g_rk);
    cudaGetSymbolAddress((void**)&qup,   g_qu);
    cudaGetSymbolAddress((void**)&qvp,   g_qv);
    cudaGetSymbolAddress((void**)&vtp,   g_vt);
    cudaGetSymbolAddress((void**)&sp,    g_S);
    cudaGetSymbolAddress((void**)&bdp,   g_BD);
    cudaGetSymbolAddress((void**)&statp, g_stat);
    cudaGetSymbolAddress((void**)&attnp, g_attn);
    cudaGetSymbolAddress((void**)&aop,   g_ao);
    cudaGetSymbolAddress((void**)&yp,    g_y);
    cudaGetSymbolAddress((void**)&yrp,   g_yr);
    cudaGetSymbolAddress((void**)&hp,    g_h);
    cudaGetSymbolAddress((void**)&zp,    g_z);
    cudaGetSymbolAddress((void**)&memr,  g_memr);
    cudaGetSymbolAddress((void**)&inr,   g_inr);
    cudaGetSymbolAddress((void**)&rr,    g_rr);
    cudaGetSymbolAddress((void**)&wqkvr, g_wqkv);
    cudaGetSymbolAddress((void**)&wrr,   g_wr);
    cudaGetSymbolAddress((void**)&wor,   g_wo);
    cudaGetSymbolAddress((void**)&w1r,   g_w1);
    cudaGetSymbolAddress((void**)&w2r,   g_w2);

    // RNA round-copies (tf32-exact operands; MMA then truncates exactly)
    auto rc = [](const float* s, float* d, int n) {
        round_copy<<<(n / 4 + 255) / 256, 256>>>(s, d, n / 4);
    };
    rc(mem,    memr,  MEMLEN * BATCH * DMODEL);
    rc(inputs, inr,   QLEN * BATCH * DMODEL);
    rc(r,      rr,    KLEN * DMODEL);
    rc(Wqkv,   wqkvr, QKVW * DMODEL);
    rc(Wr,     wrr,   DMODEL * DMODEL);
    rc(Wo,     wor,   DMODEL * DMODEL);
    rc(w1,     w1r,   DMLP * DMODEL);
    rc(w2,     w2r,   DMODEL * DMLP);

    // qkv projection (rounded out: feeds K operand / prep kernels)
    lin_gemm<<<dim3(QKVW / 128, 4096 / 128), 256>>>(memr, wqkvr, nullptr, qkvp,
                                                    DMODEL, QKVW, 4);
    lin_gemm<<<dim3(QKVW / 128, 4096 / 128), 256>>>(inr, wqkvr, nullptr,
                                                    qkvp + (size_t)4096 * QKVW,
                                                    DMODEL, QKVW, 4);
    lin_gemm<<<dim3(DMODEL / 128, KLEN / 128), 256>>>(rr, wrr, nullptr, rkp,
                                                      DMODEL, DMODEL, 4);
    prep_quv<<<dim3(QLEN, BATCH), 512>>>(qkvp, u, v, qup, qvp);
    prep_vt<<<dim3(KLEN / 32, DHEAD / 32, BH), 256>>>(qkvp, vtp);
    // scores: BD raw, then AC fused with rel-shift add + scale -> S
    score_bd<<<dim3(KLEN / 128, QLEN / 128, BH), 256>>>(qvp, rkp, bdp);
    score_ac<<<dim3(KLEN / 128, QLEN / 128, BH), 256>>>(qup, qkvp, bdp, sp);
    // softmax stats
    rowstat<<<dim3(QLEN, BH), 256>>>(sp, statp);
    // prob tuple output (exp+normalize+transpose fused)
    float* prob_out = (float*)d_out + QLEN * BATCH * DMODEL;
    probout<<<dim3(KLEN / 32, QLEN), 256>>>(sp, statp, prob_out);
    // attn = softmax(S) @ V, exp on the fly
    attn_exp_gemm<<<dim3(QLEN / 64, BH), 128>>>(sp, statp, vtp, attnp);
    lin_gemm<<<dim3(DMODEL / 128, QROWS / 128), 256>>>(attnp, wor, nullptr, aop,
                                                       DMODEL, DMODEL, 0);
    add_ln<<<QROWS, 256>>>(inputs, aop, ln1_g, ln1_b, yp, yrp);
    lin_gemm<<<dim3(DMLP / 128, QROWS / 128), 256>>>(yrp, w1r, b1, hp,
                                                     DMODEL, DMLP, 7);
    lin_gemm<<<dim3(DMODEL / 128, QROWS / 128), 256>>>(hp, w2r, b2, zp,
                                                       DMLP, DMODEL, 1);
    add_ln<<<QROWS, 256>>>(yp, zp, ln2_g, ln2_b, (float*)d_out, nullptr);
}

// round 5
// speedup vs baseline: 1.0103x; 1.0103x over previous
#include <cuda_runtime.h>
#include <math.h>

#define QLEN 1024
#define BATCH 4
#define DMODEL 512
#define HEADS 8
#define DHEAD 64
#define MEMLEN 1024
#define KLEN 2048
#define DMLP 2048
#define BH 32
#define QROWS 4096
#define KROWS 8192
#define QKVW 1536
#define QSTRIDE 6144
#define QK ((size_t)QLEN * KLEN)

// ---------------- scratch ----------------
__device__ float g_qkv[KROWS * QKVW];
__device__ float g_rk[KLEN * DMODEL];
__device__ float g_qu[BH * QLEN * DHEAD];
__device__ float g_qv[BH * QLEN * DHEAD];
__device__ float g_vt[BH * DHEAD * KLEN];
__device__ float g_S[(size_t)BH * QLEN * KLEN];
__device__ float g_BD[(size_t)BH * QLEN * KLEN];
__device__ float2 g_stat[BH * QLEN];
__device__ float g_attn[QROWS * DMODEL];
__device__ float g_ao[QROWS * DMODEL];
__device__ float g_y[QROWS * DMODEL];
__device__ float g_yr[QROWS * DMODEL];
__device__ float g_h[QROWS * DMLP];
__device__ float g_z[QROWS * DMODEL];
__device__ float g_memr[MEMLEN * BATCH * DMODEL];
__device__ float g_inr[QLEN * BATCH * DMODEL];
__device__ float g_rr[KLEN * DMODEL];
__device__ float g_wqkv[QKVW * DMODEL];
__device__ float g_wr[DMODEL * DMODEL];
__device__ float g_wo[DMODEL * DMODEL];
__device__ float g_w1[DMLP * DMODEL];
__device__ float g_w2[DMODEL * DMLP];

// ---------------- helpers ----------------
__device__ __forceinline__ float f2tf(float x) {
    unsigned r;
    asm("cvt.rna.tf32.f32 %0, %1;" : "=r"(r) : "f"(x));
    return __uint_as_float(r);
}
__device__ __forceinline__ void cp16(float* dst_smem, const float* src) {
    unsigned d = (unsigned)__cvta_generic_to_shared(dst_smem);
    asm volatile("cp.async.ca.shared.global [%0], [%1], 16;" :: "r"(d), "l"(src));
}
__device__ __forceinline__ void cp_commit() { asm volatile("cp.async.commit_group;"); }
__device__ __forceinline__ void cp_wait1()  { asm volatile("cp.async.wait_group 1;"); }
__device__ __forceinline__ void cp_wait0()  { asm volatile("cp.async.wait_group 0;"); }

__device__ __forceinline__ void mma_tf32(float* acc, unsigned a0, unsigned a1,
                                         unsigned a2, unsigned a3,
                                         unsigned b0, unsigned b1) {
    asm volatile(
        "mma.sync.aligned.m16n8k8.row.col.f32.tf32.tf32.f32 "
        "{%0,%1,%2,%3}, {%4,%5,%6,%7}, {%8,%9}, {%0,%1,%2,%3};"
        : "+f"(acc[0]), "+f"(acc[1]), "+f"(acc[2]), "+f"(acc[3])
        : "r"(a0), "r"(a1), "r"(a2), "r"(a3), "r"(b0), "r"(b1));
}

// ---------------- RNA round-copy ----------------
__global__ void round_copy(const float* __restrict__ src, float* __restrict__ dst,
                           int n4) {
    int idx = blockIdx.x * blockDim.x + threadIdx.x;
    if (idx < n4) {
        float4 v = ((const float4*)src)[idx];
        v.x = f2tf(v.x); v.y = f2tf(v.y); v.z = f2tf(v.z); v.w = f2tf(v.w);
        ((float4*)dst)[idx] = v;
    }
}

// ---------------- 128x128 tf32 NT GEMM core, 4 warps, 64x64 warp tiles -------
// acc[4][8][4]; warp layout: wm = warp&1 (M-half), wn = warp>>1 (N-half).
__device__ __forceinline__ void gemm_core128(
    const float* __restrict__ A, int lda,
    const float* __restrict__ B, int ldb,
    int K0, int K1, float acc[4][8][4])
{
    __shared__ float As[2][128][20];
    __shared__ float Bs[2][128][20];
    const int tid = threadIdx.x;          // 128 threads
    const int lane = tid & 31;
    const int warp = tid >> 5;
    const int wm = warp & 1;
    const int wn = warp >> 1;
    const int grp = lane >> 2, tig = lane & 3;

    #pragma unroll
    for (int mt = 0; mt < 4; mt++)
        #pragma unroll
        for (int nt = 0; nt < 8; nt++)
            #pragma unroll
            for (int q = 0; q < 4; q++) acc[mt][nt][q] = 0.0f;

    const int nk = (K1 - K0) >> 4;
    #pragma unroll
    for (int l = 0; l < 4; l++) {
        int idx = l * 128 + tid;
        int r = idx >> 2, c4 = (idx & 3) << 2;
        cp16(&As[0][r][c4], A + (size_t)r * lda + K0 + c4);
        cp16(&Bs[0][r][c4], B + (size_t)r * ldb + K0 + c4);
    }
    cp_commit();

    int cur = 0;
    for (int it = 0; it < nk; it++) {
        if (it + 1 < nk) {
            int kt = K0 + (it + 1) * 16;
            #pragma unroll
            for (int l = 0; l < 4; l++) {
                int idx = l * 128 + tid;
                int r = idx >> 2, c4 = (idx & 3) << 2;
                cp16(&As[cur ^ 1][r][c4], A + (size_t)r * lda + kt + c4);
                cp16(&Bs[cur ^ 1][r][c4], B + (size_t)r * ldb + kt + c4);
            }
            cp_commit();
            cp_wait1();
        } else {
            cp_wait0();
        }
        __syncthreads();
        #pragma unroll
        for (int ks = 0; ks < 16; ks += 8) {
            unsigned af[4][4], bf[8][2];
            #pragma unroll
            for (int mt = 0; mt < 4; mt++) {
                int rowb = wm * 64 + mt * 16;
                af[mt][0] = __float_as_uint(As[cur][rowb + grp][ks + tig]);
                af[mt][1] = __float_as_uint(As[cur][rowb + grp + 8][ks + tig]);
                af[mt][2] = __float_as_uint(As[cur][rowb + grp][ks + tig + 4]);
                af[mt][3] = __float_as_uint(As[cur][rowb + grp + 8][ks + tig + 4]);
            }
            #pragma unroll
            for (int nt = 0; nt < 8; nt++) {
                int colb = wn * 64 + nt * 8 + grp;
                bf[nt][0] = __float_as_uint(Bs[cur][colb][ks + tig]);
                bf[nt][1] = __float_as_uint(Bs[cur][colb][ks + tig + 4]);
            }
            #pragma unroll
            for (int mt = 0; mt < 4; mt++)
                #pragma unroll
                for (int nt = 0; nt < 8; nt++)
                    mma_tf32(acc[mt][nt], af[mt][0], af[mt][1], af[mt][2], af[mt][3],
                             bf[nt][0], bf[nt][1]);
        }
        __syncthreads();
        cur ^= 1;
    }
}

// ---------------- linear GEMM (act: +1 bias, +2 relu, +4 round-out) ----------
__global__ __launch_bounds__(128, 2) void lin_gemm(
    const float* __restrict__ A, const float* __restrict__ W,
    const float* __restrict__ bias, float* __restrict__ C,
    int K, int N, int act)
{
    int m0 = blockIdx.y * 128, n0 = blockIdx.x * 128;
    float acc[4][8][4];
    gemm_core128(A + (size_t)m0 * K, K, W + (size_t)n0 * K, K, 0, K, acc);
    const int lane = threadIdx.x & 31, warp = threadIdx.x >> 5;
    const int wm = warp & 1, wn = warp >> 1;
    const int grp = lane >> 2, tig = lane & 3;
    float* Cp = C + (size_t)m0 * N + n0;
    const float* bp = bias ? bias + n0 : nullptr;
    #pragma unroll
    for (int mt = 0; mt < 4; mt++) {
        int r0 = wm * 64 + mt * 16 + grp;
        #pragma unroll
        for (int nt = 0; nt < 8; nt++) {
            int c0 = wn * 64 + nt * 8 + tig * 2;
            float v0 = acc[mt][nt][0], v1 = acc[mt][nt][1];
            float v2 = acc[mt][nt][2], v3 = acc[mt][nt][3];
            if (act & 1) {
                float b0 = bp[c0], b1 = bp[c0 + 1];
                v0 += b0; v1 += b1; v2 += b0; v3 += b1;
            }
            if (act & 2) {
                v0 = fmaxf(v0, 0.f); v1 = fmaxf(v1, 0.f);
                v2 = fmaxf(v2, 0.f); v3 = fmaxf(v3, 0.f);
            }
            if (act & 4) {
                v0 = f2tf(v0); v1 = f2tf(v1); v2 = f2tf(v2); v3 = f2tf(v3);
            }
            *(float2*)(Cp + (size_t)r0 * N + c0) = make_float2(v0, v1);
            *(float2*)(Cp + (size_t)(r0 + 8) * N + c0) = make_float2(v2, v3);
        }
    }
}

// ---------------- BD raw scores ----------------
__global__ __launch_bounds__(128, 2) void score_bd(
    const float* __restrict__ Qv, const float* __restrict__ rk,
    float* __restrict__ BD)
{
    int bh = blockIdx.z, h = bh & 7;
    int i0 = blockIdx.y * 128, p0 = blockIdx.x * 128;
    if (p0 + i0 < 896) return;
    float acc[4][8][4];
    gemm_core128(Qv + ((size_t)bh * QLEN + i0) * DHEAD, DHEAD,
                 rk + (size_t)p0 * DMODEL + h * DHEAD, DMODEL, 0, DHEAD, acc);
    const int lane = threadIdx.x & 31, warp = threadIdx.x >> 5;
    const int wm = warp & 1, wn = warp >> 1;
    const int grp = lane >> 2, tig = lane & 3;
    float* Cp = BD + (size_t)bh * QK + (size_t)i0 * KLEN + p0;
    #pragma unroll
    for (int mt = 0; mt < 4; mt++) {
        int r0 = wm * 64 + mt * 16 + grp;
        #pragma unroll
        for (int nt = 0; nt < 8; nt++) {
            int c0 = wn * 64 + nt * 8 + tig * 2;
            *(float2*)(Cp + (size_t)r0 * KLEN + c0) =
                make_float2(acc[mt][nt][0], acc[mt][nt][1]);
            *(float2*)(Cp + (size_t)(r0 + 8) * KLEN + c0) =
                make_float2(acc[mt][nt][2], acc[mt][nt][3]);
        }
    }
}

// ---------------- AC scores fused with BD rel-shift add + scale --------------
__global__ __launch_bounds__(128, 2) void score_ac(
    const float* __restrict__ Qu, const float* __restrict__ qkv,
    const float* __restrict__ BD, float* __restrict__ S)
{
    int bh = blockIdx.z, b = bh >> 3, h = bh & 7;
    int i0 = blockIdx.y * 128, j0 = blockIdx.x * 128;
    if (j0 - i0 > 1024) return;
    float acc[4][8][4];
    gemm_core128(Qu + ((size_t)bh * QLEN + i0) * DHEAD, DHEAD,
                 qkv + (size_t)j0 * QSTRIDE + b * QKVW + DMODEL + h * DHEAD, QSTRIDE,
                 0, DHEAD, acc);
    const int lane = threadIdx.x & 31, warp = threadIdx.x >> 5;
    const int wm = warp & 1, wn = warp >> 1;
    const int grp = lane >> 2, tig = lane & 3;
    const float* bdb = BD + (size_t)bh * QK;
    float* Sp = S + (size_t)bh * QK;
    #pragma unroll
    for (int mt = 0; mt < 4; mt++) {
        #pragma unroll
        for (int hh = 0; hh < 2; hh++) {
            int gi = i0 + wm * 64 + mt * 16 + grp + hh * 8;
            const float* bdr = bdb + (size_t)gi * KLEN;
            #pragma unroll
            for (int nt = 0; nt < 8; nt++) {
                int gj = j0 + wn * 64 + nt * 8 + tig * 2;
                int p0 = min(gj - gi + (QLEN - 1), KLEN - 1);
                int p1 = min(gj + 1 - gi + (QLEN - 1), KLEN - 1);
                float v0 = (acc[mt][nt][hh * 2 + 0] + bdr[p0]) * 0.125f;
                float v1 = (acc[mt][nt][hh * 2 + 1] + bdr[p1]) * 0.125f;
                *(float2*)(Sp + (size_t)gi * KLEN + gj) = make_float2(v0, v1);
            }
        }
    }
}

// ---------------- rowstat ----------------
__global__ void rowstat(const float* __restrict__ S, float2* __restrict__ stat) {
    const int i = blockIdx.x, bh = blockIdx.y, tid = threadIdx.x;
    __shared__ float red[256];
    const float* row = S + (size_t)bh * QK + (size_t)i * KLEN;
    const int n = i + MEMLEN + 1;
    float m = -1e30f;
    for (int j = tid; j < n; j += 256) m = fmaxf(m, row[j]);
    red[tid] = m; __syncthreads();
    for (int o = 128; o > 0; o >>= 1) {
        if (tid < o) red[tid] = fmaxf(red[tid], red[tid + o]);
        __syncthreads();
    }
    m = red[0]; __syncthreads();
    float s = 0.f;
    for (int j = tid; j < n; j += 256) s += __expf(row[j] - m);
    red[tid] = s; __syncthreads();
    for (int o = 128; o > 0; o >>= 1) {
        if (tid < o) red[tid] += red[tid + o];
        __syncthreads();
    }
    if (tid == 0) stat[bh * QLEN + i] = make_float2(m, 1.0f / red[0]);
}

// ---------------- prob output: exp+normalize+transpose -> d_out[i,j,bh] ------
__global__ void probout(const float* __restrict__ S, const float2* __restrict__ stat,
                        float* __restrict__ out) {
    __shared__ float t[32][33];
    __shared__ float m_s[32], inv_s[32];
    const int i = blockIdx.y, j0 = blockIdx.x * 32;
    const int tid = threadIdx.x;
    if (tid < 32) {
        float2 st = stat[tid * QLEN + i];
        m_s[tid] = st.x; inv_s[tid] = st.y;
    }
    __syncthreads();
    const int lj = tid & 31, lb = tid >> 5;
    const int jmax = i + MEMLEN;
    #pragma unroll
    for (int r = 0; r < 4; r++) {
        int bh = r * 8 + lb;
        int j = j0 + lj;
        float val = 0.0f;
        if (j <= jmax)
            val = __expf(S[((size_t)bh * QLEN + i) * KLEN + j] - m_s[bh]) * inv_s[bh];
        t[lj][bh] = val;
    }
    __syncthreads();
    const int lbh = tid & 31, ljw = tid >> 5;
    #pragma unroll
    for (int r = 0; r < 4; r++) {
        int jj = r * 8 + ljw;
        out[((size_t)i * KLEN + j0 + jj) * 32 + lbh] = t[jj][lbh];
    }
}

// ---------------- attention: exp(S) on the fly @ Vt, 128x64 tile --------------
__global__ __launch_bounds__(128, 2) void attn_exp_gemm(
    const float* __restrict__ S, const float2* __restrict__ stat,
    const float* __restrict__ Vt, float* __restrict__ attn)
{
    const int bh = blockIdx.y, b = bh >> 3, h = bh & 7;
    const int i0 = blockIdx.x * 128;
    __shared__ float As[128][20];
    __shared__ float Bs[2][64][20];
    __shared__ float m_s[128], inv_s[128];
    const int tid = threadIdx.x;          // 128 threads, 4 warps (2M x 2N)
    const int lane = tid & 31, warp = tid >> 5;
    const int wm = warp & 1, wn = warp >> 1;
    const int grp = lane >> 2, tig = lane & 3;
    {
        float2 st = stat[bh * QLEN + i0 + tid];
        m_s[tid] = st.x; inv_s[tid] = st.y;
    }
    __syncthreads();

    const float* Srow = S + (size_t)bh * QK + (size_t)i0 * KLEN;
    const float* Vb = Vt + (size_t)bh * DHEAD * KLEN;
    const int K1 = min(KLEN, i0 + 128 + MEMLEN);
    const int nk = K1 >> 4;

    float acc[4][4][4];
    #pragma unroll
    for (int mt = 0; mt < 4; mt++)
        #pragma unroll
        for (int nt = 0; nt < 4; nt++)
            #pragma unroll
            for (int q = 0; q < 4; q++) acc[mt][nt][q] = 0.f;

    float4 aReg[4];
    #pragma unroll
    for (int l = 0; l < 4; l++) {
        int idx = l * 128 + tid;
        int r = idx >> 2, c4 = (idx & 3) << 2;
        aReg[l] = *(const float4*)(Srow + (size_t)r * KLEN + c4);
    }
    #pragma unroll
    for (int l = 0; l < 2; l++) {
        int idx = l * 128 + tid;
        int r = idx >> 2, c4 = (idx & 3) << 2;
        cp16(&Bs[0][r][c4], Vb + (size_t)r * KLEN + c4);
    }
    cp_commit();

    int cur = 0;
    for (int it = 0; it < nk; it++) {
        const int kt = it * 16;
        float4 aNext[4];
        if (it + 1 < nk) {
            int ktn = kt + 16;
            #pragma unroll
            for (int l = 0; l < 2; l++) {
                int idx = l * 128 + tid;
                int r = idx >> 2, c4 = (idx & 3) << 2;
                cp16(&Bs[cur ^ 1][r][c4], Vb + (size_t)r * KLEN + ktn + c4);
            }
            #pragma unroll
            for (int l = 0; l < 4; l++) {
                int idx = l * 128 + tid;
                int r = idx >> 2, c4 = (idx & 3) << 2;
                aNext[l] = *(const float4*)(Srow + (size_t)r * KLEN + ktn + c4);
            }
            cp_commit();
        }
        #pragma unroll
        for (int l = 0; l < 4; l++) {
            int idx = l * 128 + tid;
            int r = idx >> 2, c4 = (idx & 3) << 2;
            float mr = m_s[r];
            int jmax = i0 + r + MEMLEN;
            As[r][c4]     = (kt + c4 + 0 <= jmax) ? f2tf(__expf(aReg[l].x - mr)) : 0.f;
            As[r][c4 + 1] = (kt + c4 + 1 <= jmax) ? f2tf(__expf(aReg[l].y - mr)) : 0.f;
            As[r][c4 + 2] = (kt + c4 + 2 <= jmax) ? f2tf(__expf(aReg[l].z - mr)) : 0.f;
            As[r][c4 + 3] = (kt + c4 + 3 <= jmax) ? f2tf(__expf(aReg[l].w - mr)) : 0.f;
        }
        if (it + 1 < nk) cp_wait1(); else cp_wait0();
        __syncthreads();
        #pragma unroll
        for (int ks = 0; ks < 16; ks += 8) {
            unsigned af[4][4], bf[4][2];
            #pragma unroll
            for (int mt = 0; mt < 4; mt++) {
                int rowb = wm * 64 + mt * 16;
                af[mt][0] = __float_as_uint(As[rowb + grp][ks + tig]);
                af[mt][1] = __float_as_uint(As[rowb + grp + 8][ks + tig]);
                af[mt][2] = __float_as_uint(As[rowb + grp][ks + tig + 4]);
                af[mt][3] = __float_as_uint(As[rowb + grp + 8][ks + tig + 4]);
            }
            #pragma unroll
            for (int nt = 0; nt < 4; nt++) {
                int colb = wn * 32 + nt * 8 + grp;
                bf[nt][0] = __float_as_uint(Bs[cur][colb][ks + tig]);
                bf[nt][1] = __float_as_uint(Bs[cur][colb][ks + tig + 4]);
            }
            #pragma unroll
            for (int mt = 0; mt < 4; mt++)
                #pragma unroll
                for (int nt = 0; nt < 4; nt++)
                    mma_tf32(acc[mt][nt], af[mt][0], af[mt][1], af[mt][2], af[mt][3],
                             bf[nt][0], bf[nt][1]);
        }
        __syncthreads();
        #pragma unroll
        for (int l = 0; l < 4; l++) aReg[l] = aNext[l];
        cur ^= 1;
    }

    #pragma unroll
    for (int mt = 0; mt < 4; mt++) {
        int r0 = wm * 64 + mt * 16 + grp;
        float iv0 = inv_s[r0], iv1 = inv_s[r0 + 8];
        #pragma unroll
        for (int nt = 0; nt < 4; nt++) {
            int c0 = wn * 32 + nt * 8 + tig * 2;
            float v0 = f2tf(acc[mt][nt][0] * iv0);
            float v1 = f2tf(acc[mt][nt][1] * iv0);
            float v2 = f2tf(acc[mt][nt][2] * iv1);
            float v3 = f2tf(acc[mt][nt][3] * iv1);
            size_t o0 = ((size_t)(i0 + r0) * BATCH + b) * DMODEL + h * DHEAD + c0;
            size_t o1 = ((size_t)(i0 + r0 + 8) * BATCH + b) * DMODEL + h * DHEAD + c0;
            *(float2*)(attn + o0) = make_float2(v0, v1);
            *(float2*)(attn + o1) = make_float2(v2, v3);
        }
    }
}

// ---------------- prep: Qu/Qv (rounded) ----------------
__global__ void prep_quv(const float* __restrict__ qkv, const float* __restrict__ u,
                         const float* __restrict__ v, float* __restrict__ Qu,
                         float* __restrict__ Qv) {
    int i = blockIdx.x, b = blockIdx.y, t = threadIdx.x;
    float q = qkv[(size_t)(MEMLEN + i) * QSTRIDE + b * QKVW + t];
    int h = t >> 6, d = t & 63;
    size_t o = ((size_t)(b * HEADS + h) * QLEN + i) * DHEAD + d;
    Qu[o] = f2tf(q + u[t]);
    Qv[o] = f2tf(q + v[t]);
}

// ---------------- prep: Vt[bh][d][j] ----------------
__global__ void prep_vt(const float* __restrict__ qkv, float* __restrict__ Vt) {
    __shared__ float t[32][33];
    int bh = blockIdx.z, b = bh >> 3, h = bh & 7;
    int j0 = blockIdx.x * 32, d0 = blockIdx.y * 32;
    int tc = threadIdx.x & 31, tr = threadIdx.x >> 5;
    #pragma unroll
    for (int rr = 0; rr < 32; rr += 8)
        t[tr + rr][tc] = qkv[(size_t)(j0 + tr + rr) * QSTRIDE + b * QKVW
                             + 2 * DMODEL + h * DHEAD + d0 + tc];
    __syncthreads();
    #pragma unroll
    for (int rr = 0; rr < 32; rr += 8)
        Vt[((size_t)bh * DHEAD + d0 + tr + rr) * KLEN + j0 + tc] = t[tc][tr + rr];
}

// ---------------- residual add + layernorm ----------------
__global__ void add_ln(const float* __restrict__ x1, const float* __restrict__ x2,
                       const float* __restrict__ g, const float* __restrict__ bb,
                       float* __restrict__ out, float* __restrict__ out_r) {
    const int row = blockIdx.x;
    const int tid = threadIdx.x;
    __shared__ float red[256];
    __shared__ float red2[256];
    const float* a = x1 + (size_t)row * DMODEL;
    const float* c = x2 + (size_t)row * DMODEL;
    float v0 = a[tid] + c[tid];
    float v1 = a[tid + 256] + c[tid + 256];
    red[tid] = v0 + v1;
    red2[tid] = v0 * v0 + v1 * v1;
    __syncthreads();
    for (int o = 128; o > 0; o >>= 1) {
        if (tid < o) { red[tid] += red[tid + o]; red2[tid] += red2[tid + o]; }
        __syncthreads();
    }
    const float mu = red[0] * (1.0f / DMODEL);
    const float var = red2[0] * (1.0f / DMODEL) - mu * mu;
    const float rstd = rsqrtf(var + 1e-5f);
    float* o = out + (size_t)row * DMODEL;
    float r0 = (v0 - mu) * rstd * g[tid] + bb[tid];
    float r1 = (v1 - mu) * rstd * g[tid + 256] + bb[tid + 256];
    o[tid] = r0;
    o[tid + 256] = r1;
    if (out_r) {
        float* orr = out_r + (size_t)row * DMODEL;
        orr[tid] = f2tf(r0);
        orr[tid + 256] = f2tf(r1);
    }
}

// ---------------- launch ----------------
extern "C" void kernel_launch(void* const* d_in, const int* in_sizes, int n_in,
                              void* d_out, int out_size) {
    const float* inputs = (const float*)d_in[0];
    const float* r      = (const float*)d_in[1];
    const float* u      = (const float*)d_in[2];
    const float* v      = (const float*)d_in[3];
    const float* mem    = (const float*)d_in[4];
    const float* Wqkv   = (const float*)d_in[6];
    const float* Wr     = (const float*)d_in[7];
    const float* Wo     = (const float*)d_in[8];
    const float* ln1_g  = (const float*)d_in[9];
    const float* ln1_b  = (const float*)d_in[10];
    const float* w1     = (const float*)d_in[11];
    const float* b1     = (const float*)d_in[12];
    const float* w2     = (const float*)d_in[13];
    const float* b2     = (const float*)d_in[14];
    const float* ln2_g  = (const float*)d_in[15];
    const float* ln2_b  = (const float*)d_in[16];

    float *qkvp, *rkp, *qup, *qvp, *vtp, *sp, *bdp, *attnp, *aop, *yp, *yrp, *hp, *zp;
    float *memr, *inr, *rr, *wqkvr, *wrr, *wor, *w1r, *w2r;
    float2* statp;
    cudaGetSymbolAddress((void**)&qkvp,  g_qkv);
    cudaGetSymbolAddress((void**)&rkp,   g_rk);
    cudaGetSymbolAddress((void**)&qup,   g_qu);
    cudaGetSymbolAddress((void**)&qvp,   g_qv);
    cudaGetSymbolAddress((void**)&vtp,   g_vt);
    cudaGetSymbolAddress((void**)&sp,    g_S);
    cudaGetSymbolAddress((void**)&bdp,   g_BD);
    cudaGetSymbolAddress((void**)&statp, g_stat);
    cudaGetSymbolAddress((void**)&attnp, g_attn);
    cudaGetSymbolAddress((void**)&aop,   g_ao);
    cudaGetSymbolAddress((void**)&yp,    g_y);
    cudaGetSymbolAddress((void**)&yrp,   g_yr);
    cudaGetSymbolAddress((void**)&hp,    g_h);
    cudaGetSymbolAddress((void**)&zp,    g_z);
    cudaGetSymbolAddress((void**)&memr,  g_memr);
    cudaGetSymbolAddress((void**)&inr,   g_inr);
    cudaGetSymbolAddress((void**)&rr,    g_rr);
    cudaGetSymbolAddress((void**)&wqkvr, g_wqkv);
    cudaGetSymbolAddress((void**)&wrr,   g_wr);
    cudaGetSymbolAddress((void**)&wor,   g_wo);
    cudaGetSymbolAddress((void**)&w1r,   g_w1);
    cudaGetSymbolAddress((void**)&w2r,   g_w2);

    auto rc = [](const float* s, float* d, int n) {
        round_copy<<<(n / 4 + 255) / 256, 256>>>(s, d, n / 4);
    };
    rc(mem,    memr,  MEMLEN * BATCH * DMODEL);
    rc(inputs, inr,   QLEN * BATCH * DMODEL);
    rc(r,      rr,    KLEN * DMODEL);
    rc(Wqkv,   wqkvr, QKVW * DMODEL);
    rc(Wr,     wrr,   DMODEL * DMODEL);
    rc(Wo,     wor,   DMODEL * DMODEL);
    rc(w1,     w1r,   DMLP * DMODEL);
    rc(w2,     w2r,   DMODEL * DMLP);

    lin_gemm<<<dim3(QKVW / 128, 4096 / 128), 128>>>(memr, wqkvr, nullptr, qkvp,
                                                    DMODEL, QKVW, 4);
    lin_gemm<<<dim3(QKVW / 128, 4096 / 128), 128>>>(inr, wqkvr, nullptr,
                                                    qkvp + (size_t)4096 * QKVW,
                                                    DMODEL, QKVW, 4);
    lin_gemm<<<dim3(DMODEL / 128, KLEN / 128), 128>>>(rr, wrr, nullptr, rkp,
                                                      DMODEL, DMODEL, 4);
    prep_quv<<<dim3(QLEN, BATCH), 512>>>(qkvp, u, v, qup, qvp);
    prep_vt<<<dim3(KLEN / 32, DHEAD / 32, BH), 256>>>(qkvp, vtp);
    score_bd<<<dim3(KLEN / 128, QLEN / 128, BH), 128>>>(qvp, rkp, bdp);
    score_ac<<<dim3(KLEN / 128, QLEN / 128, BH), 128>>>(qup, qkvp, bdp, sp);
    rowstat<<<dim3(QLEN, BH), 256>>>(sp, statp);
    float* prob_out = (float*)d_out + QLEN * BATCH * DMODEL;
    probout<<<dim3(KLEN / 32, QLEN), 256>>>(sp, statp, prob_out);
    attn_exp_gemm<<<dim3(QLEN / 128, BH), 128>>>(sp, statp, vtp, attnp);
    lin_gemm<<<dim3(DMODEL / 128, QROWS / 128), 128>>>(attnp, wor, nullptr, aop,
                                                       DMODEL, DMODEL, 0);
    add_ln<<<QROWS, 256>>>(inputs, aop, ln1_g, ln1_b, yp, yrp);
    lin_gemm<<<dim3(DMLP / 128, QROWS / 128), 128>>>(yrp, w1r, b1, hp,
                                                     DMODEL, DMLP, 7);
    lin_gemm<<<dim3(DMODEL / 128, QROWS / 128), 128>>>(hp, w2r, b2, zp,
                                                       DMLP, DMODEL, 1);
    add_ln<<<QROWS, 256>>>(yp, zp, ln2_g, ln2_b, (float*)d_out, nullptr);
}

// round 6
// speedup vs baseline: 1.0284x; 1.0179x over previous
#include <cuda_runtime.h>
#include <math.h>

#define QLEN 1024
#define BATCH 4
#define DMODEL 512
#define HEADS 8
#define DHEAD 64
#define MEMLEN 1024
#define KLEN 2048
#define DMLP 2048
#define BH 32
#define QROWS 4096
#define KROWS 8192
#define QKVW 1536
#define QSTRIDE 6144
#define QK ((size_t)QLEN * KLEN)
#define SMEM_DYN 61440   // 3 stages * (128+128) rows * 20 floats * 4B

// ---------------- scratch ----------------
__device__ float g_qkv[KROWS * QKVW];
__device__ float g_rk[KLEN * DMODEL];
__device__ float g_qu[BH * QLEN * DHEAD];
__device__ float g_qv[BH * QLEN * DHEAD];
__device__ float g_vt[BH * DHEAD * KLEN];
__device__ float g_S[(size_t)BH * QLEN * KLEN];
__device__ float g_BD[(size_t)BH * QLEN * KLEN];
__device__ float2 g_part[(size_t)BH * QLEN * 16];
__device__ float2 g_stat[BH * QLEN];
__device__ float g_attn[QROWS * DMODEL];
__device__ float g_ao[QROWS * DMODEL];
__device__ float g_y[QROWS * DMODEL];
__device__ float g_yr[QROWS * DMODEL];
__device__ float g_h[QROWS * DMLP];
__device__ float g_z[QROWS * DMODEL];
__device__ float g_rnd[8650752];   // concatenated RNA-rounded inputs/weights

// rounded-buffer float offsets
#define OFF_MEM  0
#define OFF_IN   2097152
#define OFF_R    4194304
#define OFF_WQKV 5242880
#define OFF_WR   6029312
#define OFF_WO   6291456
#define OFF_W1   6553600
#define OFF_W2   7602176

// ---------------- helpers ----------------
__device__ __forceinline__ float f2tf(float x) {
    unsigned r;
    asm("cvt.rna.tf32.f32 %0, %1;" : "=r"(r) : "f"(x));
    return __uint_as_float(r);
}
__device__ __forceinline__ void cp16(float* dst_smem, const float* src) {
    unsigned d = (unsigned)__cvta_generic_to_shared(dst_smem);
    asm volatile("cp.async.ca.shared.global [%0], [%1], 16;" :: "r"(d), "l"(src));
}
__device__ __forceinline__ void cp_commit() { asm volatile("cp.async.commit_group;"); }
__device__ __forceinline__ void cp_wait1()  { asm volatile("cp.async.wait_group 1;"); }
__device__ __forceinline__ void cp_wait0()  { asm volatile("cp.async.wait_group 0;"); }

__device__ __forceinline__ void mma_tf32(float* acc, unsigned a0, unsigned a1,
                                         unsigned a2, unsigned a3,
                                         unsigned b0, unsigned b1) {
    asm volatile(
        "mma.sync.aligned.m16n8k8.row.col.f32.tf32.tf32.f32 "
        "{%0,%1,%2,%3}, {%4,%5,%6,%7}, {%8,%9}, {%0,%1,%2,%3};"
        : "+f"(acc[0]), "+f"(acc[1]), "+f"(acc[2]), "+f"(acc[3])
        : "r"(a0), "r"(a1), "r"(a2), "r"(a3), "r"(b0), "r"(b1));
}

// ---------------- fused RNA round-copy of all tf32 operands -------------------
__global__ void round_all(const float* __restrict__ s0, const float* __restrict__ s1,
                          const float* __restrict__ s2, const float* __restrict__ s3,
                          const float* __restrict__ s4, const float* __restrict__ s5,
                          const float* __restrict__ s6, const float* __restrict__ s7,
                          float4* __restrict__ dst) {
    int idx = blockIdx.x * 256 + threadIdx.x;   // float4 units
    if (idx >= 2162688) return;
    const float4* src; int base;
    if      (idx < 524288)  { src = (const float4*)s0; base = 0; }
    else if (idx < 1048576) { src = (const float4*)s1; base = 524288; }
    else if (idx < 1310720) { src = (const float4*)s2; base = 1048576; }
    else if (idx < 1507328) { src = (const float4*)s3; base = 1310720; }
    else if (idx < 1572864) { src = (const float4*)s4; base = 1507328; }
    else if (idx < 1638400) { src = (const float4*)s5; base = 1572864; }
    else if (idx < 1900544) { src = (const float4*)s6; base = 1638400; }
    else                    { src = (const float4*)s7; base = 1900544; }
    float4 v = src[idx - base];
    v.x = f2tf(v.x); v.y = f2tf(v.y); v.z = f2tf(v.z); v.w = f2tf(v.w);
    dst[idx] = v;
}

// ---------------- 128x128 tf32 NT GEMM core: 3-stage cp.async, 4 warps -------
__device__ __forceinline__ void gemm_core128(
    const float* __restrict__ A, int lda,
    const float* __restrict__ B, int ldb,
    int K0, int K1, float acc[4][8][4], float* sm)
{
    const int tid = threadIdx.x;
    const int lane = tid & 31, warp = tid >> 5;
    const int wm = warp & 1, wn = warp >> 1;
    const int grp = lane >> 2, tig = lane & 3;

    #pragma unroll
    for (int mt = 0; mt < 4; mt++)
        #pragma unroll
        for (int nt = 0; nt < 8; nt++)
            #pragma unroll
            for (int q = 0; q < 4; q++) acc[mt][nt][q] = 0.0f;

    const int nk = (K1 - K0) >> 4;

    auto load = [&](int it, int s) {
        int kt = K0 + it * 16;
        float* as = sm + s * 2560;
        float* bs = sm + 7680 + s * 2560;
        #pragma unroll
        for (int l = 0; l < 4; l++) {
            int idx = l * 128 + tid;
            int r = idx >> 2, c4 = (idx & 3) << 2;
            cp16(as + r * 20 + c4, A + (size_t)r * lda + kt + c4);
            cp16(bs + r * 20 + c4, B + (size_t)r * ldb + kt + c4);
        }
        cp_commit();
    };

    load(0, 0);
    if (nk > 1) load(1, 1);

    for (int it = 0; it < nk; it++) {
        if (it + 1 < nk) cp_wait1(); else cp_wait0();
        __syncthreads();
        if (it + 2 < nk) load(it + 2, (it + 2) % 3);
        const float* as = sm + (it % 3) * 2560;
        const float* bs = sm + 7680 + (it % 3) * 2560;
        #pragma unroll
        for (int ks = 0; ks < 16; ks += 8) {
            unsigned af[4][4], bf[8][2];
            #pragma unroll
            for (int mt = 0; mt < 4; mt++) {
                int rowb = wm * 64 + mt * 16;
                af[mt][0] = __float_as_uint(as[(rowb + grp) * 20 + ks + tig]);
                af[mt][1] = __float_as_uint(as[(rowb + grp + 8) * 20 + ks + tig]);
                af[mt][2] = __float_as_uint(as[(rowb + grp) * 20 + ks + tig + 4]);
                af[mt][3] = __float_as_uint(as[(rowb + grp + 8) * 20 + ks + tig + 4]);
            }
            #pragma unroll
            for (int nt = 0; nt < 8; nt++) {
                int colb = wn * 64 + nt * 8 + grp;
                bf[nt][0] = __float_as_uint(bs[colb * 20 + ks + tig]);
                bf[nt][1] = __float_as_uint(bs[colb * 20 + ks + tig + 4]);
            }
            #pragma unroll
            for (int mt = 0; mt < 4; mt++)
                #pragma unroll
                for (int nt = 0; nt < 8; nt++)
                    mma_tf32(acc[mt][nt], af[mt][0], af[mt][1], af[mt][2], af[mt][3],
                             bf[nt][0], bf[nt][1]);
        }
    }
}

// ---------------- linear GEMM (act: +1 bias, +2 relu, +4 round-out) ----------
__global__ __launch_bounds__(128, 2) void lin_gemm(
    const float* __restrict__ A, const float* __restrict__ W,
    const float* __restrict__ bias, float* __restrict__ C,
    int K, int N, int act)
{
    extern __shared__ float sm[];
    int m0 = blockIdx.y * 128, n0 = blockIdx.x * 128;
    float acc[4][8][4];
    gemm_core128(A + (size_t)m0 * K, K, W + (size_t)n0 * K, K, 0, K, acc, sm);
    const int lane = threadIdx.x & 31, warp = threadIdx.x >> 5;
    const int wm = warp & 1, wn = warp >> 1;
    const int grp = lane >> 2, tig = lane & 3;
    float* Cp = C + (size_t)m0 * N + n0;
    const float* bp = bias ? bias + n0 : nullptr;
    #pragma unroll
    for (int mt = 0; mt < 4; mt++) {
        int r0 = wm * 64 + mt * 16 + grp;
        #pragma unroll
        for (int nt = 0; nt < 8; nt++) {
            int c0 = wn * 64 + nt * 8 + tig * 2;
            float v0 = acc[mt][nt][0], v1 = acc[mt][nt][1];
            float v2 = acc[mt][nt][2], v3 = acc[mt][nt][3];
            if (act & 1) {
                float b0 = bp[c0], b1 = bp[c0 + 1];
                v0 += b0; v1 += b1; v2 += b0; v3 += b1;
            }
            if (act & 2) {
                v0 = fmaxf(v0, 0.f); v1 = fmaxf(v1, 0.f);
                v2 = fmaxf(v2, 0.f); v3 = fmaxf(v3, 0.f);
            }
            if (act & 4) {
                v0 = f2tf(v0); v1 = f2tf(v1); v2 = f2tf(v2); v3 = f2tf(v3);
            }
            *(float2*)(Cp + (size_t)r0 * N + c0) = make_float2(v0, v1);
            *(float2*)(Cp + (size_t)(r0 + 8) * N + c0) = make_float2(v2, v3);
        }
    }
}

// ---------------- BD raw scores ----------------
__global__ __launch_bounds__(128, 2) void score_bd(
    const float* __restrict__ Qv, const float* __restrict__ rk,
    float* __restrict__ BD)
{
    extern __shared__ float sm[];
    int bh = blockIdx.z, h = bh & 7;
    int i0 = blockIdx.y * 128, p0 = blockIdx.x * 128;
    if (p0 + i0 < 896) return;
    float acc[4][8][4];
    gemm_core128(Qv + ((size_t)bh * QLEN + i0) * DHEAD, DHEAD,
                 rk + (size_t)p0 * DMODEL + h * DHEAD, DMODEL, 0, DHEAD, acc, sm);
    const int lane = threadIdx.x & 31, warp = threadIdx.x >> 5;
    const int wm = warp & 1, wn = warp >> 1;
    const int grp = lane >> 2, tig = lane & 3;
    float* Cp = BD + (size_t)bh * QK + (size_t)i0 * KLEN + p0;
    #pragma unroll
    for (int mt = 0; mt < 4; mt++) {
        int r0 = wm * 64 + mt * 16 + grp;
        #pragma unroll
        for (int nt = 0; nt < 8; nt++) {
            int c0 = wn * 64 + nt * 8 + tig * 2;
            *(float2*)(Cp + (size_t)r0 * KLEN + c0) =
                make_float2(acc[mt][nt][0], acc[mt][nt][1]);
            *(float2*)(Cp + (size_t)(r0 + 8) * KLEN + c0) =
                make_float2(acc[mt][nt][2], acc[mt][nt][3]);
        }
    }
}

// ---------------- AC scores + BD rel-shift + scale + per-tile softmax partials
__global__ __launch_bounds__(128, 2) void score_ac(
    const float* __restrict__ Qu, const float* __restrict__ qkv,
    const float* __restrict__ BD, float* __restrict__ S,
    float2* __restrict__ part_out)
{
    extern __shared__ float sm[];
    int bh = blockIdx.z, b = bh >> 3, h = bh & 7;
    int i0 = blockIdx.y * 128, j0 = blockIdx.x * 128;
    if (j0 - i0 > 1024) return;
    float acc[4][8][4];
    gemm_core128(Qu + ((size_t)bh * QLEN + i0) * DHEAD, DHEAD,
                 qkv + (size_t)j0 * QSTRIDE + b * QKVW + DMODEL + h * DHEAD, QSTRIDE,
                 0, DHEAD, acc, sm);
    const int tid = threadIdx.x;
    const int lane = tid & 31, warp = tid >> 5;
    const int wm = warp & 1, wn = warp >> 1;
    const int grp = lane >> 2, tig = lane & 3;
    const float* bdb = BD + (size_t)bh * QK;
    float* Sp = S + (size_t)bh * QK;

    // finalize values in acc, write S
    #pragma unroll
    for (int mt = 0; mt < 4; mt++) {
        #pragma unroll
        for (int hh = 0; hh < 2; hh++) {
            int gi = i0 + wm * 64 + mt * 16 + grp + hh * 8;
            const float* bdr = bdb + (size_t)gi * KLEN;
            int jmax = gi + MEMLEN;
            #pragma unroll
            for (int nt = 0; nt < 8; nt++) {
                int gj = j0 + wn * 64 + nt * 8 + tig * 2;
                int p0 = min(gj - gi + (QLEN - 1), KLEN - 1);
                int p1 = min(p0 + 1, KLEN - 1);
                float v0 = (gj     <= jmax) ? (acc[mt][nt][hh*2+0] + bdr[p0]) * 0.125f : -1e30f;
                float v1 = (gj + 1 <= jmax) ? (acc[mt][nt][hh*2+1] + bdr[p1]) * 0.125f : -1e30f;
                acc[mt][nt][hh*2+0] = v0;
                acc[mt][nt][hh*2+1] = v1;
                *(float2*)(Sp + (size_t)gi * KLEN + gj) = make_float2(v0, v1);
            }
        }
    }

    // per-tile row softmax partials: (max, expsum)
    __syncthreads();                 // smem free after core's last reads
    float2* part = (float2*)sm;      // [2 wn][128 rows]
    #pragma unroll
    for (int mt = 0; mt < 4; mt++) {
        #pragma unroll
        for (int hh = 0; hh < 2; hh++) {
            float m = -1e30f;
            #pragma unroll
            for (int nt = 0; nt < 8; nt++) {
                m = fmaxf(m, acc[mt][nt][hh*2+0]);
                m = fmaxf(m, acc[mt][nt][hh*2+1]);
            }
            float s = 0.f;
            #pragma unroll
            for (int nt = 0; nt < 8; nt++) {
                s += __expf(acc[mt][nt][hh*2+0] - m);
                s += __expf(acc[mt][nt][hh*2+1] - m);
            }
            #pragma unroll
            for (int o = 1; o < 4; o <<= 1) {
                float m2 = __shfl_xor_sync(0xffffffffu, m, o);
                float s2 = __shfl_xor_sync(0xffffffffu, s, o);
                float mm = fmaxf(m, m2);
                s = s * __expf(m - mm) + s2 * __expf(m2 - mm);
                m = mm;
            }
            if (tig == 0)
                part[wn * 128 + wm * 64 + mt * 16 + hh * 8 + grp] = make_float2(m, s);
        }
    }
    __syncthreads();
    {
        float2 a = part[tid], c = part[128 + tid];
        float mm = fmaxf(a.x, c.x);
        float ss = a.y * __expf(a.x - mm) + c.y * __expf(c.x - mm);
        part_out[((size_t)bh * QLEN + i0 + tid) * 16 + (j0 >> 7)] = make_float2(mm, ss);
    }
}

// ---------------- combine per-tile partials into row stats --------------------
__global__ void statcombine(const float2* __restrict__ part, float2* __restrict__ stat) {
    int id = blockIdx.x * 256 + threadIdx.x;
    if (id >= BH * QLEN) return;
    int i = id & (QLEN - 1);
    int ntl = (i >> 7) + 9; if (ntl > 16) ntl = 16;
    float M = -1e30f, Ssum = 0.f;
    const float2* p = part + (size_t)id * 16;
    for (int t = 0; t < ntl; t++) {
        float2 q = p[t];
        float mm = fmaxf(M, q.x);
        Ssum = Ssum * __expf(M - mm) + q.y * __expf(q.x - mm);
        M = mm;
    }
    stat[id] = make_float2(M, 1.0f / Ssum);
}

// ---------------- prob output: exp+normalize+transpose -> d_out[i,j,bh] ------
__global__ void probout(const float* __restrict__ S, const float2* __restrict__ stat,
                        float* __restrict__ out) {
    __shared__ float t[32][33];
    __shared__ float m_s[32], inv_s[32];
    const int i = blockIdx.y, j0 = blockIdx.x * 32;
    const int tid = threadIdx.x;
    if (tid < 32) {
        float2 st = stat[tid * QLEN + i];
        m_s[tid] = st.x; inv_s[tid] = st.y;
    }
    __syncthreads();
    const int lj = tid & 31, lb = tid >> 5;
    const int jmax = i + MEMLEN;
    #pragma unroll
    for (int r = 0; r < 4; r++) {
        int bh = r * 8 + lb;
        int j = j0 + lj;
        float val = 0.0f;
        if (j <= jmax)
            val = __expf(S[((size_t)bh * QLEN + i) * KLEN + j] - m_s[bh]) * inv_s[bh];
        t[lj][bh] = val;
    }
    __syncthreads();
    const int lbh = tid & 31, ljw = tid >> 5;
    #pragma unroll
    for (int r = 0; r < 4; r++) {
        int jj = r * 8 + ljw;
        out[((size_t)i * KLEN + j0 + jj) * 32 + lbh] = t[jj][lbh];
    }
}

// ---------------- attention: exp(S) on the fly @ Vt, 128x64 tile --------------
__global__ __launch_bounds__(128, 2) void attn_exp_gemm(
    const float* __restrict__ S, const float2* __restrict__ stat,
    const float* __restrict__ Vt, float* __restrict__ attn)
{
    const int bh = blockIdx.y, b = bh >> 3, h = bh & 7;
    const int i0 = blockIdx.x * 128;
    __shared__ float As[128][20];
    __shared__ float Bs[2][64][20];
    __shared__ float m_s[128], inv_s[128];
    const int tid = threadIdx.x;
    const int lane = tid & 31, warp = tid >> 5;
    const int wm = warp & 1, wn = warp >> 1;
    const int grp = lane >> 2, tig = lane & 3;
    {
        float2 st = stat[bh * QLEN + i0 + tid];
        m_s[tid] = st.x; inv_s[tid] = st.y;
    }
    __syncthreads();

    const float* Srow = S + (size_t)bh * QK + (size_t)i0 * KLEN;
    const float* Vb = Vt + (size_t)bh * DHEAD * KLEN;
    const int K1 = min(KLEN, i0 + 128 + MEMLEN);
    const int nk = K1 >> 4;

    float acc[4][4][4];
    #pragma unroll
    for (int mt = 0; mt < 4; mt++)
        #pragma unroll
        for (int nt = 0; nt < 4; nt++)
            #pragma unroll
            for (int q = 0; q < 4; q++) acc[mt][nt][q] = 0.f;

    float4 aReg[4];
    #pragma unroll
    for (int l = 0; l < 4; l++) {
        int idx = l * 128 + tid;
        int r = idx >> 2, c4 = (idx & 3) << 2;
        aReg[l] = *(const float4*)(Srow + (size_t)r * KLEN + c4);
    }
    #pragma unroll
    for (int l = 0; l < 2; l++) {
        int idx = l * 128 + tid;
        int r = idx >> 2, c4 = (idx & 3) << 2;
        cp16(&Bs[0][r][c4], Vb + (size_t)r * KLEN + c4);
    }
    cp_commit();

    int cur = 0;
    for (int it = 0; it < nk; it++) {
        const int kt = it * 16;
        float4 aNext[4];
        if (it + 1 < nk) {
            int ktn = kt + 16;
            #pragma unroll
            for (int l = 0; l < 2; l++) {
                int idx = l * 128 + tid;
                int r = idx >> 2, c4 = (idx & 3) << 2;
                cp16(&Bs[cur ^ 1][r][c4], Vb + (size_t)r * KLEN + ktn + c4);
            }
            #pragma unroll
            for (int l = 0; l < 4; l++) {
                int idx = l * 128 + tid;
                int r = idx >> 2, c4 = (idx & 3) << 2;
                aNext[l] = *(const float4*)(Srow + (size_t)r * KLEN + ktn + c4);
            }
            cp_commit();
        }
        #pragma unroll
        for (int l = 0; l < 4; l++) {
            int idx = l * 128 + tid;
            int r = idx >> 2, c4 = (idx & 3) << 2;
            float mr = m_s[r];
            int jmax = i0 + r + MEMLEN;
            As[r][c4]     = (kt + c4 + 0 <= jmax) ? f2tf(__expf(aReg[l].x - mr)) : 0.f;
            As[r][c4 + 1] = (kt + c4 + 1 <= jmax) ? f2tf(__expf(aReg[l].y - mr)) : 0.f;
            As[r][c4 + 2] = (kt + c4 + 2 <= jmax) ? f2tf(__expf(aReg[l].z - mr)) : 0.f;
            As[r][c4 + 3] = (kt + c4 + 3 <= jmax) ? f2tf(__expf(aReg[l].w - mr)) : 0.f;
        }
        if (it + 1 < nk) cp_wait1(); else cp_wait0();
        __syncthreads();
        #pragma unroll
        for (int ks = 0; ks < 16; ks += 8) {
            unsigned af[4][4], bf[4][2];
            #pragma unroll
            for (int mt = 0; mt < 4; mt++) {
                int rowb = wm * 64 + mt * 16;
                af[mt][0] = __float_as_uint(As[rowb + grp][ks + tig]);
                af[mt][1] = __float_as_uint(As[rowb + grp + 8][ks + tig]);
                af[mt][2] = __float_as_uint(As[rowb + grp][ks + tig + 4]);
                af[mt][3] = __float_as_uint(As[rowb + grp + 8][ks + tig + 4]);
            }
            #pragma unroll
            for (int nt = 0; nt < 4; nt++) {
                int colb = wn * 32 + nt * 8 + grp;
                bf[nt][0] = __float_as_uint(Bs[cur][colb][ks + tig]);
                bf[nt][1] = __float_as_uint(Bs[cur][colb][ks + tig + 4]);
            }
            #pragma unroll
            for (int mt = 0; mt < 4; mt++)
                #pragma unroll
                for (int nt = 0; nt < 4; nt++)
                    mma_tf32(acc[mt][nt], af[mt][0], af[mt][1], af[mt][2], af[mt][3],
                             bf[nt][0], bf[nt][1]);
        }
        __syncthreads();
        #pragma unroll
        for (int l = 0; l < 4; l++) aReg[l] = aNext[l];
        cur ^= 1;
    }

    #pragma unroll
    for (int mt = 0; mt < 4; mt++) {
        int r0 = wm * 64 + mt * 16 + grp;
        float iv0 = inv_s[r0], iv1 = inv_s[r0 + 8];
        #pragma unroll
        for (int nt = 0; nt < 4; nt++) {
            int c0 = wn * 32 + nt * 8 + tig * 2;
            float v0 = f2tf(acc[mt][nt][0] * iv0);
            float v1 = f2tf(acc[mt][nt][1] * iv0);
            float v2 = f2tf(acc[mt][nt][2] * iv1);
            float v3 = f2tf(acc[mt][nt][3] * iv1);
            size_t o0 = ((size_t)(i0 + r0) * BATCH + b) * DMODEL + h * DHEAD + c0;
            size_t o1 = ((size_t)(i0 + r0 + 8) * BATCH + b) * DMODEL + h * DHEAD + c0;
            *(float2*)(attn + o0) = make_float2(v0, v1);
            *(float2*)(attn + o1) = make_float2(v2, v3);
        }
    }
}

// ---------------- prep: Qu/Qv (rounded) ----------------
__global__ void prep_quv(const float* __restrict__ qkv, const float* __restrict__ u,
                         const float* __restrict__ v, float* __restrict__ Qu,
                         float* __restrict__ Qv) {
    int i = blockIdx.x, b = blockIdx.y, t = threadIdx.x;
    float q = qkv[(size_t)(MEMLEN + i) * QSTRIDE + b * QKVW + t];
    int h = t >> 6, d = t & 63;
    size_t o = ((size_t)(b * HEADS + h) * QLEN + i) * DHEAD + d;
    Qu[o] = f2tf(q + u[t]);
    Qv[o] = f2tf(q + v[t]);
}

// ---------------- prep: Vt[bh][d][j] ----------------
__global__ void prep_vt(const float* __restrict__ qkv, float* __restrict__ Vt) {
    __shared__ float t[32][33];
    int bh = blockIdx.z, b = bh >> 3, h = bh & 7;
    int j0 = blockIdx.x * 32, d0 = blockIdx.y * 32;
    int tc = threadIdx.x & 31, tr = threadIdx.x >> 5;
    #pragma unroll
    for (int rr = 0; rr < 32; rr += 8)
        t[tr + rr][tc] = qkv[(size_t)(j0 + tr + rr) * QSTRIDE + b * QKVW
                             + 2 * DMODEL + h * DHEAD + d0 + tc];
    __syncthreads();
    #pragma unroll
    for (int rr = 0; rr < 32; rr += 8)
        Vt[((size_t)bh * DHEAD + d0 + tr + rr) * KLEN + j0 + tc] = t[tc][tr + rr];
}

// ---------------- residual add + layernorm ----------------
__global__ void add_ln(const float* __restrict__ x1, const float* __restrict__ x2,
                       const float* __restrict__ g, const float* __restrict__ bb,
                       float* __restrict__ out, float* __restrict__ out_r) {
    const int row = blockIdx.x;
    const int tid = threadIdx.x;
    __shared__ float red[256];
    __shared__ float red2[256];
    const float* a = x1 + (size_t)row * DMODEL;
    const float* c = x2 + (size_t)row * DMODEL;
    float v0 = a[tid] + c[tid];
    float v1 = a[tid + 256] + c[tid + 256];
    red[tid] = v0 + v1;
    red2[tid] = v0 * v0 + v1 * v1;
    __syncthreads();
    for (int o = 128; o > 0; o >>= 1) {
        if (tid < o) { red[tid] += red[tid + o]; red2[tid] += red2[tid + o]; }
        __syncthreads();
    }
    const float mu = red[0] * (1.0f / DMODEL);
    const float var = red2[0] * (1.0f / DMODEL) - mu * mu;
    const float rstd = rsqrtf(var + 1e-5f);
    float* o = out + (size_t)row * DMODEL;
    float r0 = (v0 - mu) * rstd * g[tid] + bb[tid];
    float r1 = (v1 - mu) * rstd * g[tid + 256] + bb[tid + 256];
    o[tid] = r0;
    o[tid + 256] = r1;
    if (out_r) {
        float* orr = out_r + (size_t)row * DMODEL;
        orr[tid] = f2tf(r0);
        orr[tid + 256] = f2tf(r1);
    }
}

// ---------------- launch ----------------
extern "C" void kernel_launch(void* const* d_in, const int* in_sizes, int n_in,
                              void* d_out, int out_size) {
    const float* inputs = (const float*)d_in[0];
    const float* r      = (const float*)d_in[1];
    const float* u      = (const float*)d_in[2];
    const float* v      = (const float*)d_in[3];
    const float* mem    = (const float*)d_in[4];
    const float* Wqkv   = (const float*)d_in[6];
    const float* Wr     = (const float*)d_in[7];
    const float* Wo     = (const float*)d_in[8];
    const float* ln1_g  = (const float*)d_in[9];
    const float* ln1_b  = (const float*)d_in[10];
    const float* w1     = (const float*)d_in[11];
    const float* b1     = (const float*)d_in[12];
    const float* w2     = (const float*)d_in[13];
    const float* b2     = (const float*)d_in[14];
    const float* ln2_g  = (const float*)d_in[15];
    const float* ln2_b  = (const float*)d_in[16];

    static bool attr_done = false;
    if (!attr_done) {
        cudaFuncSetAttribute(lin_gemm, cudaFuncAttributeMaxDynamicSharedMemorySize, SMEM_DYN);
        cudaFuncSetAttribute(score_bd, cudaFuncAttributeMaxDynamicSharedMemorySize, SMEM_DYN);
        cudaFuncSetAttribute(score_ac, cudaFuncAttributeMaxDynamicSharedMemorySize, SMEM_DYN);
        attr_done = true;
    }

    float *qkvp, *rkp, *qup, *qvp, *vtp, *sp, *bdp, *attnp, *aop, *yp, *yrp, *hp, *zp, *rnd;
    float2 *statp, *partp;
    cudaGetSymbolAddress((void**)&qkvp,  g_qkv);
    cudaGetSymbolAddress((void**)&rkp,   g_rk);
    cudaGetSymbolAddress((void**)&qup,   g_qu);
    cudaGetSymbolAddress((void**)&qvp,   g_qv);
    cudaGetSymbolAddress((void**)&vtp,   g_vt);
    cudaGetSymbolAddress((void**)&sp,    g_S);
    cudaGetSymbolAddress((void**)&bdp,   g_BD);
    cudaGetSymbolAddress((void**)&statp, g_stat);
    cudaGetSymbolAddress((void**)&partp, g_part);
    cudaGetSymbolAddress((void**)&attnp, g_attn);
    cudaGetSymbolAddress((void**)&aop,   g_ao);
    cudaGetSymbolAddress((void**)&yp,    g_y);
    cudaGetSymbolAddress((void**)&yrp,   g_yr);
    cudaGetSymbolAddress((void**)&hp,    g_h);
    cudaGetSymbolAddress((void**)&zp,    g_z);
    cudaGetSymbolAddress((void**)&rnd,   g_rnd);

    const float* memr  = rnd + OFF_MEM;
    const float* inr   = rnd + OFF_IN;
    const float* rr    = rnd + OFF_R;
    const float* wqkvr = rnd + OFF_WQKV;
    const float* wrr   = rnd + OFF_WR;
    const float* wor   = rnd + OFF_WO;
    const float* w1r   = rnd + OFF_W1;
    const float* w2r   = rnd + OFF_W2;

    // 1: fused RNA rounding of all tf32 operands
    round_all<<<(2162688 + 255) / 256, 256>>>(mem, inputs, r, Wqkv, Wr, Wo, w1, w2,
                                              (float4*)rnd);
    // 2-4: projections
    lin_gemm<<<dim3(QKVW / 128, 4096 / 128), 128, SMEM_DYN>>>(memr, wqkvr, nullptr, qkvp,
                                                              DMODEL, QKVW, 4);
    lin_gemm<<<dim3(QKVW / 128, 4096 / 128), 128, SMEM_DYN>>>(inr, wqkvr, nullptr,
                                                              qkvp + (size_t)4096 * QKVW,
                                                              DMODEL, QKVW, 4);
    lin_gemm<<<dim3(DMODEL / 128, KLEN / 128), 128, SMEM_DYN>>>(rr, wrr, nullptr, rkp,
                                                                DMODEL, DMODEL, 4);
    // 5: Q extraction   6: score_bd (profiled launch)
    prep_quv<<<dim3(QLEN, BATCH), 512>>>(qkvp, u, v, qup, qvp);
    score_bd<<<dim3(KLEN / 128, QLEN / 128, BH), 128, SMEM_DYN>>>(qvp, rkp, bdp);
    // 7-9
    prep_vt<<<dim3(KLEN / 32, DHEAD / 32, BH), 256>>>(qkvp, vtp);
    score_ac<<<dim3(KLEN / 128, QLEN / 128, BH), 128, SMEM_DYN>>>(qup, qkvp, bdp, sp, partp);
    statcombine<<<(BH * QLEN + 255) / 256, 256>>>(partp, statp);
    // 10: prob tuple output
    float* prob_out = (float*)d_out + QLEN * BATCH * DMODEL;
    probout<<<dim3(KLEN / 32, QLEN), 256>>>(sp, statp, prob_out);
    // 11-16
    attn_exp_gemm<<<dim3(QLEN / 128, BH), 128>>>(sp, statp, vtp, attnp);
    lin_gemm<<<dim3(DMODEL / 128, QROWS / 128), 128, SMEM_DYN>>>(attnp, wor, nullptr, aop,
                                                                 DMODEL, DMODEL, 0);
    add_ln<<<QROWS, 256>>>(inputs, aop, ln1_g, ln1_b, yp, yrp);
    lin_gemm<<<dim3(DMLP / 128, QROWS / 128), 128, SMEM_DYN>>>(yrp, w1r, b1, hp,
                                                               DMODEL, DMLP, 7);
    lin_gemm<<<dim3(DMODEL / 128, QROWS / 128), 128, SMEM_DYN>>>(hp, w2r, b2, zp,
                                                                 DMLP, DMODEL, 1);
    add_ln<<<QROWS, 256>>>(yp, zp, ln2_g, ln2_b, (float*)d_out, nullptr);
}

// round 7
// speedup vs baseline: 1.0393x; 1.0106x over previous
#include <cuda_runtime.h>
#include <math.h>

#define QLEN 1024
#define BATCH 4
#define DMODEL 512
#define HEADS 8
#define DHEAD 64
#define MEMLEN 1024
#define KLEN 2048
#define DMLP 2048
#define BH 32
#define QROWS 4096
#define KROWS 8192
#define QKVW 1536
#define QSTRIDE 6144
#define QK ((size_t)QLEN * KLEN)
#define SMEM_DYN 61440   // 3 stages * (128+128) rows * 20 floats * 4B

// ---------------- scratch ----------------
__device__ float g_qkv[KROWS * QKVW];
__device__ float g_rk[KLEN * DMODEL];
__device__ float g_qu[BH * QLEN * DHEAD];
__device__ float g_qv[BH * QLEN * DHEAD];
__device__ float g_vt[BH * DHEAD * KLEN];
__device__ float g_S[(size_t)BH * QLEN * KLEN];
__device__ float g_BD[(size_t)BH * QLEN * KLEN];
__device__ float2 g_part[(size_t)BH * QLEN * 16];
__device__ float2 g_stat[BH * QLEN];
__device__ float g_attn[QROWS * DMODEL];
__device__ float g_ao[QROWS * DMODEL];
__device__ float g_y[QROWS * DMODEL];
__device__ float g_yr[QROWS * DMODEL];
__device__ float g_h[QROWS * DMLP];
__device__ float g_z[QROWS * DMODEL];
__device__ float g_rnd[8650752];   // concatenated RNA-rounded inputs/weights

#define OFF_MEM  0
#define OFF_IN   2097152
#define OFF_R    4194304
#define OFF_WQKV 5242880
#define OFF_WR   6029312
#define OFF_WO   6291456
#define OFF_W1   6553600
#define OFF_W2   7602176

// ---------------- helpers ----------------
__device__ __forceinline__ float f2tf(float x) {
    unsigned r;
    asm("cvt.rna.tf32.f32 %0, %1;" : "=r"(r) : "f"(x));
    return __uint_as_float(r);
}
__device__ __forceinline__ void cp16(float* dst_smem, const float* src) {
    unsigned d = (unsigned)__cvta_generic_to_shared(dst_smem);
    asm volatile("cp.async.ca.shared.global [%0], [%1], 16;" :: "r"(d), "l"(src));
}
__device__ __forceinline__ void cp_commit() { asm volatile("cp.async.commit_group;"); }
__device__ __forceinline__ void cp_wait1()  { asm volatile("cp.async.wait_group 1;"); }
__device__ __forceinline__ void cp_wait0()  { asm volatile("cp.async.wait_group 0;"); }

__device__ __forceinline__ void mma_tf32(float* acc, unsigned a0, unsigned a1,
                                         unsigned a2, unsigned a3,
                                         unsigned b0, unsigned b1) {
    asm volatile(
        "mma.sync.aligned.m16n8k8.row.col.f32.tf32.tf32.f32 "
        "{%0,%1,%2,%3}, {%4,%5,%6,%7}, {%8,%9}, {%0,%1,%2,%3};"
        : "+f"(acc[0]), "+f"(acc[1]), "+f"(acc[2]), "+f"(acc[3])
        : "r"(a0), "r"(a1), "r"(a2), "r"(a3), "r"(b0), "r"(b1));
}
// ldmatrix x4: 16 rows x 8 tf32 cols; r0..r3 = tf32 mma A-fragment order
__device__ __forceinline__ void ldsm_x4(unsigned& r0, unsigned& r1, unsigned& r2,
                                        unsigned& r3, unsigned addr) {
    asm volatile("ldmatrix.sync.aligned.m8n8.x4.shared.b16 {%0,%1,%2,%3}, [%4];"
                 : "=r"(r0), "=r"(r1), "=r"(r2), "=r"(r3) : "r"(addr));
}

// ---------------- fused RNA round-copy ----------------
__global__ void round_all(const float* __restrict__ s0, const float* __restrict__ s1,
                          const float* __restrict__ s2, const float* __restrict__ s3,
                          const float* __restrict__ s4, const float* __restrict__ s5,
                          const float* __restrict__ s6, const float* __restrict__ s7,
                          float4* __restrict__ dst) {
    int idx = blockIdx.x * 256 + threadIdx.x;
    if (idx >= 2162688) return;
    const float4* src; int base;
    if      (idx < 524288)  { src = (const float4*)s0; base = 0; }
    else if (idx < 1048576) { src = (const float4*)s1; base = 524288; }
    else if (idx < 1310720) { src = (const float4*)s2; base = 1048576; }
    else if (idx < 1507328) { src = (const float4*)s3; base = 1310720; }
    else if (idx < 1572864) { src = (const float4*)s4; base = 1507328; }
    else if (idx < 1638400) { src = (const float4*)s5; base = 1572864; }
    else if (idx < 1900544) { src = (const float4*)s6; base = 1638400; }
    else                    { src = (const float4*)s7; base = 1900544; }
    float4 v = src[idx - base];
    v.x = f2tf(v.x); v.y = f2tf(v.y); v.z = f2tf(v.z); v.w = f2tf(v.w);
    dst[idx] = v;
}

// ---------------- 128x128 tf32 NT GEMM core: 3-stage cp.async + ldmatrix -----
__device__ __forceinline__ void gemm_core128(
    const float* __restrict__ A, int lda,
    const float* __restrict__ B, int ldb,
    int K0, int K1, float acc[4][8][4], float* sm)
{
    const int tid = threadIdx.x;
    const int lane = tid & 31, warp = tid >> 5;
    const int wm = warp & 1, wn = warp >> 1;

    #pragma unroll
    for (int mt = 0; mt < 4; mt++)
        #pragma unroll
        for (int nt = 0; nt < 8; nt++)
            #pragma unroll
            for (int q = 0; q < 4; q++) acc[mt][nt][q] = 0.0f;

    const int nk = (K1 - K0) >> 4;

    auto load = [&](int it, int s) {
        int kt = K0 + it * 16;
        float* as = sm + s * 2560;
        float* bs = sm + 7680 + s * 2560;
        #pragma unroll
        for (int l = 0; l < 4; l++) {
            int idx = l * 128 + tid;
            int r = idx >> 2, c4 = (idx & 3) << 2;
            cp16(as + r * 20 + c4, A + (size_t)r * lda + kt + c4);
            cp16(bs + r * 20 + c4, B + (size_t)r * ldb + kt + c4);
        }
        cp_commit();
    };

    load(0, 0);
    if (nk > 1) load(1, 1);

    const unsigned smem_u = (unsigned)__cvta_generic_to_shared(sm);
    const int rowsel = lane & 15;
    const int colsel = (lane >> 4) << 2;
    const unsigned aOff = (unsigned)((wm * 64 + rowsel) * 20 + colsel);
    const unsigned bOff = (unsigned)(7680 + (wn * 64 + rowsel) * 20 + colsel);

    for (int it = 0; it < nk; it++) {
        if (it + 1 < nk) cp_wait1(); else cp_wait0();
        __syncthreads();
        if (it + 2 < nk) load(it + 2, (it + 2) % 3);
        const unsigned stageOff = (unsigned)((it % 3) * 2560);
        const unsigned aS = smem_u + (stageOff + aOff) * 4;
        const unsigned bS = smem_u + (stageOff + bOff) * 4;
        #pragma unroll
        for (int ks = 0; ks < 16; ks += 8) {
            unsigned af[4][4], bf[8][2];
            #pragma unroll
            for (int mt = 0; mt < 4; mt++)
                ldsm_x4(af[mt][0], af[mt][1], af[mt][2], af[mt][3],
                        aS + (mt * 16 * 20 + ks) * 4);
            #pragma unroll
            for (int p = 0; p < 4; p++) {
                unsigned r0, r1, r2, r3;
                ldsm_x4(r0, r1, r2, r3, bS + (p * 16 * 20 + ks) * 4);
                bf[2*p][0] = r0; bf[2*p+1][0] = r1;
                bf[2*p][1] = r2; bf[2*p+1][1] = r3;
            }
            #pragma unroll
            for (int mt = 0; mt < 4; mt++)
                #pragma unroll
                for (int nt = 0; nt < 8; nt++)
                    mma_tf32(acc[mt][nt], af[mt][0], af[mt][1], af[mt][2], af[mt][3],
                             bf[nt][0], bf[nt][1]);
        }
    }
}

// ---------------- linear GEMM (act: +1 bias, +2 relu, +4 round-out) ----------
__global__ __launch_bounds__(128, 2) void lin_gemm(
    const float* __restrict__ A, const float* __restrict__ W,
    const float* __restrict__ bias, float* __restrict__ C,
    int K, int N, int act)
{
    extern __shared__ float sm[];
    int m0 = blockIdx.y * 128, n0 = blockIdx.x * 128;
    float acc[4][8][4];
    gemm_core128(A + (size_t)m0 * K, K, W + (size_t)n0 * K, K, 0, K, acc, sm);
    const int lane = threadIdx.x & 31, warp = threadIdx.x >> 5;
    const int wm = warp & 1, wn = warp >> 1;
    const int grp = lane >> 2, tig = lane & 3;
    float* Cp = C + (size_t)m0 * N + n0;
    const float* bp = bias ? bias + n0 : nullptr;
    #pragma unroll
    for (int mt = 0; mt < 4; mt++) {
        int r0 = wm * 64 + mt * 16 + grp;
        #pragma unroll
        for (int nt = 0; nt < 8; nt++) {
            int c0 = wn * 64 + nt * 8 + tig * 2;
            float v0 = acc[mt][nt][0], v1 = acc[mt][nt][1];
            float v2 = acc[mt][nt][2], v3 = acc[mt][nt][3];
            if (act & 1) {
                float b0 = bp[c0], b1 = bp[c0 + 1];
                v0 += b0; v1 += b1; v2 += b0; v3 += b1;
            }
            if (act & 2) {
                v0 = fmaxf(v0, 0.f); v1 = fmaxf(v1, 0.f);
                v2 = fmaxf(v2, 0.f); v3 = fmaxf(v3, 0.f);
            }
            if (act & 4) {
                v0 = f2tf(v0); v1 = f2tf(v1); v2 = f2tf(v2); v3 = f2tf(v3);
            }
            *(float2*)(Cp + (size_t)r0 * N + c0) = make_float2(v0, v1);
            *(float2*)(Cp + (size_t)(r0 + 8) * N + c0) = make_float2(v2, v3);
        }
    }
}

// ---------------- BD raw scores ----------------
__global__ __launch_bounds__(128, 2) void score_bd(
    const float* __restrict__ Qv, const float* __restrict__ rk,
    float* __restrict__ BD)
{
    extern __shared__ float sm[];
    int bh = blockIdx.z, h = bh & 7;
    int i0 = blockIdx.y * 128, p0 = blockIdx.x * 128;
    if (p0 + i0 < 896) return;
    float acc[4][8][4];
    gemm_core128(Qv + ((size_t)bh * QLEN + i0) * DHEAD, DHEAD,
                 rk + (size_t)p0 * DMODEL + h * DHEAD, DMODEL, 0, DHEAD, acc, sm);
    const int lane = threadIdx.x & 31, warp = threadIdx.x >> 5;
    const int wm = warp & 1, wn = warp >> 1;
    const int grp = lane >> 2, tig = lane & 3;
    float* Cp = BD + (size_t)bh * QK + (size_t)i0 * KLEN + p0;
    #pragma unroll
    for (int mt = 0; mt < 4; mt++) {
        int r0 = wm * 64 + mt * 16 + grp;
        #pragma unroll
        for (int nt = 0; nt < 8; nt++) {
            int c0 = wn * 64 + nt * 8 + tig * 2;
            *(float2*)(Cp + (size_t)r0 * KLEN + c0) =
                make_float2(acc[mt][nt][0], acc[mt][nt][1]);
            *(float2*)(Cp + (size_t)(r0 + 8) * KLEN + c0) =
                make_float2(acc[mt][nt][2], acc[mt][nt][3]);
        }
    }
}

// ---------------- AC scores + BD rel-shift + scale + softmax partials --------
__global__ __launch_bounds__(128, 2) void score_ac(
    const float* __restrict__ Qu, const float* __restrict__ qkv,
    const float* __restrict__ BD, float* __restrict__ S,
    float2* __restrict__ part_out)
{
    extern __shared__ float sm[];
    int bh = blockIdx.z, b = bh >> 3, h = bh & 7;
    int i0 = blockIdx.y * 128, j0 = blockIdx.x * 128;
    if (j0 - i0 > 1024) return;
    float acc[4][8][4];
    gemm_core128(Qu + ((size_t)bh * QLEN + i0) * DHEAD, DHEAD,
                 qkv + (size_t)j0 * QSTRIDE + b * QKVW + DMODEL + h * DHEAD, QSTRIDE,
                 0, DHEAD, acc, sm);
    const int tid = threadIdx.x;
    const int lane = tid & 31, warp = tid >> 5;
    const int wm = warp & 1, wn = warp >> 1;
    const int grp = lane >> 2, tig = lane & 3;
    const float* bdb = BD + (size_t)bh * QK;
    float* Sp = S + (size_t)bh * QK;

    #pragma unroll
    for (int mt = 0; mt < 4; mt++) {
        #pragma unroll
        for (int hh = 0; hh < 2; hh++) {
            int gi = i0 + wm * 64 + mt * 16 + grp + hh * 8;
            const float* bdr = bdb + (size_t)gi * KLEN;
            int jmax = gi + MEMLEN;
            #pragma unroll
            for (int nt = 0; nt < 8; nt++) {
                int gj = j0 + wn * 64 + nt * 8 + tig * 2;
                int p0 = min(gj - gi + (QLEN - 1), KLEN - 1);
                int p1 = min(p0 + 1, KLEN - 1);
                float v0 = (gj     <= jmax) ? (acc[mt][nt][hh*2+0] + bdr[p0]) * 0.125f : -1e30f;
                float v1 = (gj + 1 <= jmax) ? (acc[mt][nt][hh*2+1] + bdr[p1]) * 0.125f : -1e30f;
                acc[mt][nt][hh*2+0] = v0;
                acc[mt][nt][hh*2+1] = v1;
                *(float2*)(Sp + (size_t)gi * KLEN + gj) = make_float2(v0, v1);
            }
        }
    }

    __syncthreads();
    float2* part = (float2*)sm;
    #pragma unroll
    for (int mt = 0; mt < 4; mt++) {
        #pragma unroll
        for (int hh = 0; hh < 2; hh++) {
            float m = -1e30f;
            #pragma unroll
            for (int nt = 0; nt < 8; nt++) {
                m = fmaxf(m, acc[mt][nt][hh*2+0]);
                m = fmaxf(m, acc[mt][nt][hh*2+1]);
            }
            float s = 0.f;
            #pragma unroll
            for (int nt = 0; nt < 8; nt++) {
                s += __expf(acc[mt][nt][hh*2+0] - m);
                s += __expf(acc[mt][nt][hh*2+1] - m);
            }
            #pragma unroll
            for (int o = 1; o < 4; o <<= 1) {
                float m2 = __shfl_xor_sync(0xffffffffu, m, o);
                float s2 = __shfl_xor_sync(0xffffffffu, s, o);
                float mm = fmaxf(m, m2);
                s = s * __expf(m - mm) + s2 * __expf(m2 - mm);
                m = mm;
            }
            if (tig == 0)
                part[wn * 128 + wm * 64 + mt * 16 + hh * 8 + grp] = make_float2(m, s);
        }
    }
    __syncthreads();
    {
        float2 a = part[tid], c = part[128 + tid];
        float mm = fmaxf(a.x, c.x);
        float ss = a.y * __expf(a.x - mm) + c.y * __expf(c.x - mm);
        part_out[((size_t)bh * QLEN + i0 + tid) * 16 + (j0 >> 7)] = make_float2(mm, ss);
    }
}

// ---------------- combine partials ----------------
__global__ void statcombine(const float2* __restrict__ part, float2* __restrict__ stat) {
    int id = blockIdx.x * 256 + threadIdx.x;
    if (id >= BH * QLEN) return;
    int i = id & (QLEN - 1);
    int ntl = (i >> 7) + 9; if (ntl > 16) ntl = 16;
    float M = -1e30f, Ssum = 0.f;
    const float2* p = part + (size_t)id * 16;
    for (int t = 0; t < ntl; t++) {
        float2 q = p[t];
        float mm = fmaxf(M, q.x);
        Ssum = Ssum * __expf(M - mm) + q.y * __expf(q.x - mm);
        M = mm;
    }
    stat[id] = make_float2(M, 1.0f / Ssum);
}

// ---------------- prob output ----------------
__global__ void probout(const float* __restrict__ S, const float2* __restrict__ stat,
                        float* __restrict__ out) {
    __shared__ float t[32][33];
    __shared__ float m_s[32], inv_s[32];
    const int i = blockIdx.y, j0 = blockIdx.x * 32;
    const int tid = threadIdx.x;
    if (tid < 32) {
        float2 st = stat[tid * QLEN + i];
        m_s[tid] = st.x; inv_s[tid] = st.y;
    }
    __syncthreads();
    const int lj = tid & 31, lb = tid >> 5;
    const int jmax = i + MEMLEN;
    #pragma unroll
    for (int r = 0; r < 4; r++) {
        int bh = r * 8 + lb;
        int j = j0 + lj;
        float val = 0.0f;
        if (j <= jmax)
            val = __expf(S[((size_t)bh * QLEN + i) * KLEN + j] - m_s[bh]) * inv_s[bh];
        t[lj][bh] = val;
    }
    __syncthreads();
    const int lbh = tid & 31, ljw = tid >> 5;
    #pragma unroll
    for (int r = 0; r < 4; r++) {
        int jj = r * 8 + ljw;
        out[((size_t)i * KLEN + j0 + jj) * 32 + lbh] = t[jj][lbh];
    }
}

// ---------------- attention: exp(S) on the fly @ Vt (ldmatrix frags) ----------
__global__ __launch_bounds__(128, 2) void attn_exp_gemm(
    const float* __restrict__ S, const float2* __restrict__ stat,
    const float* __restrict__ Vt, float* __restrict__ attn)
{
    const int bh = blockIdx.y, b = bh >> 3, h = bh & 7;
    const int i0 = blockIdx.x * 128;
    __shared__ __align__(16) float As[128][20];
    __shared__ __align__(16) float Bs[2][64][20];
    __shared__ float m_s[128], inv_s[128];
    const int tid = threadIdx.x;
    const int lane = tid & 31, warp = tid >> 5;
    const int wm = warp & 1, wn = warp >> 1;
    const int grp = lane >> 2, tig = lane & 3;
    {
        float2 st = stat[bh * QLEN + i0 + tid];
        m_s[tid] = st.x; inv_s[tid] = st.y;
    }
    __syncthreads();

    const float* Srow = S + (size_t)bh * QK + (size_t)i0 * KLEN;
    const float* Vb = Vt + (size_t)bh * DHEAD * KLEN;
    const int K1 = min(KLEN, i0 + 128 + MEMLEN);
    const int nk = K1 >> 4;

    float acc[4][4][4];
    #pragma unroll
    for (int mt = 0; mt < 4; mt++)
        #pragma unroll
        for (int nt = 0; nt < 4; nt++)
            #pragma unroll
            for (int q = 0; q < 4; q++) acc[mt][nt][q] = 0.f;

    float4 aReg[4];
    #pragma unroll
    for (int l = 0; l < 4; l++) {
        int idx = l * 128 + tid;
        int r = idx >> 2, c4 = (idx & 3) << 2;
        aReg[l] = *(const float4*)(Srow + (size_t)r * KLEN + c4);
    }
    #pragma unroll
    for (int l = 0; l < 2; l++) {
        int idx = l * 128 + tid;
        int r = idx >> 2, c4 = (idx & 3) << 2;
        cp16(&Bs[0][r][c4], Vb + (size_t)r * KLEN + c4);
    }
    cp_commit();

    const unsigned aBase = (unsigned)__cvta_generic_to_shared(&As[0][0]);
    const unsigned bBase = (unsigned)__cvta_generic_to_shared(&Bs[0][0][0]);
    const int rowsel = lane & 15;
    const int colsel = (lane >> 4) << 2;
    const unsigned aOff = aBase + (unsigned)(((wm * 64 + rowsel) * 20 + colsel) * 4);
    const unsigned bOff = bBase + (unsigned)(((wn * 32 + rowsel) * 20 + colsel) * 4);

    int cur = 0;
    for (int it = 0; it < nk; it++) {
        const int kt = it * 16;
        float4 aNext[4];
        if (it + 1 < nk) {
            int ktn = kt + 16;
            #pragma unroll
            for (int l = 0; l < 2; l++) {
                int idx = l * 128 + tid;
                int r = idx >> 2, c4 = (idx & 3) << 2;
                cp16(&Bs[cur ^ 1][r][c4], Vb + (size_t)r * KLEN + ktn + c4);
            }
            #pragma unroll
            for (int l = 0; l < 4; l++) {
                int idx = l * 128 + tid;
                int r = idx >> 2, c4 = (idx & 3) << 2;
                aNext[l] = *(const float4*)(Srow + (size_t)r * KLEN + ktn + c4);
            }
            cp_commit();
        }
        #pragma unroll
        for (int l = 0; l < 4; l++) {
            int idx = l * 128 + tid;
            int r = idx >> 2, c4 = (idx & 3) << 2;
            float mr = m_s[r];
            int jmax = i0 + r + MEMLEN;
            As[r][c4]     = (kt + c4 + 0 <= jmax) ? f2tf(__expf(aReg[l].x - mr)) : 0.f;
            As[r][c4 + 1] = (kt + c4 + 1 <= jmax) ? f2tf(__expf(aReg[l].y - mr)) : 0.f;
            As[r][c4 + 2] = (kt + c4 + 2 <= jmax) ? f2tf(__expf(aReg[l].z - mr)) : 0.f;
            As[r][c4 + 3] = (kt + c4 + 3 <= jmax) ? f2tf(__expf(aReg[l].w - mr)) : 0.f;
        }
        if (it + 1 < nk) cp_wait1(); else cp_wait0();
        __syncthreads();
        const unsigned bS = bOff + (unsigned)(cur * 64 * 20 * 4);
        #pragma unroll
        for (int ks = 0; ks < 16; ks += 8) {
            unsigned af[4][4], bf[4][2];
            #pragma unroll
            for (int mt = 0; mt < 4; mt++)
                ldsm_x4(af[mt][0], af[mt][1], af[mt][2], af[mt][3],
                        aOff + (mt * 16 * 20 + ks) * 4);
            #pragma unroll
            for (int p = 0; p < 2; p++) {
                unsigned r0, r1, r2, r3;
                ldsm_x4(r0, r1, r2, r3, bS + (p * 16 * 20 + ks) * 4);
                bf[2*p][0] = r0; bf[2*p+1][0] = r1;
                bf[2*p][1] = r2; bf[2*p+1][1] = r3;
            }
            #pragma unroll
            for (int mt = 0; mt < 4; mt++)
                #pragma unroll
                for (int nt = 0; nt < 4; nt++)
                    mma_tf32(acc[mt][nt], af[mt][0], af[mt][1], af[mt][2], af[mt][3],
                             bf[nt][0], bf[nt][1]);
        }
        __syncthreads();
        #pragma unroll
        for (int l = 0; l < 4; l++) aReg[l] = aNext[l];
        cur ^= 1;
    }

    #pragma unroll
    for (int mt = 0; mt < 4; mt++) {
        int r0 = wm * 64 + mt * 16 + grp;
        float iv0 = inv_s[r0], iv1 = inv_s[r0 + 8];
        #pragma unroll
        for (int nt = 0; nt < 4; nt++) {
            int c0 = wn * 32 + nt * 8 + tig * 2;
            float v0 = f2tf(acc[mt][nt][0] * iv0);
            float v1 = f2tf(acc[mt][nt][1] * iv0);
            float v2 = f2tf(acc[mt][nt][2] * iv1);
            float v3 = f2tf(acc[mt][nt][3] * iv1);
            size_t o0 = ((size_t)(i0 + r0) * BATCH + b) * DMODEL + h * DHEAD + c0;
            size_t o1 = ((size_t)(i0 + r0 + 8) * BATCH + b) * DMODEL + h * DHEAD + c0;
            *(float2*)(attn + o0) = make_float2(v0, v1);
            *(float2*)(attn + o1) = make_float2(v2, v3);
        }
    }
}

// ---------------- prep: Qu/Qv (rounded) ----------------
__global__ void prep_quv(const float* __restrict__ qkv, const float* __restrict__ u,
                         const float* __restrict__ v, float* __restrict__ Qu,
                         float* __restrict__ Qv) {
    int i = blockIdx.x, b = blockIdx.y, t = threadIdx.x;
    float q = qkv[(size_t)(MEMLEN + i) * QSTRIDE + b * QKVW + t];
    int h = t >> 6, d = t & 63;
    size_t o = ((size_t)(b * HEADS + h) * QLEN + i) * DHEAD + d;
    Qu[o] = f2tf(q + u[t]);
    Qv[o] = f2tf(q + v[t]);
}

// ---------------- prep: Vt[bh][d][j] ----------------
__global__ void prep_vt(const float* __restrict__ qkv, float* __restrict__ Vt) {
    __shared__ float t[32][33];
    int bh = blockIdx.z, b = bh >> 3, h = bh & 7;
    int j0 = blockIdx.x * 32, d0 = blockIdx.y * 32;
    int tc = threadIdx.x & 31, tr = threadIdx.x >> 5;
    #pragma unroll
    for (int rr = 0; rr < 32; rr += 8)
        t[tr + rr][tc] = qkv[(size_t)(j0 + tr + rr) * QSTRIDE + b * QKVW
                             + 2 * DMODEL + h * DHEAD + d0 + tc];
    __syncthreads();
    #pragma unroll
    for (int rr = 0; rr < 32; rr += 8)
        Vt[((size_t)bh * DHEAD + d0 + tr + rr) * KLEN + j0 + tc] = t[tc][tr + rr];
}

// ---------------- residual add + layernorm ----------------
__global__ void add_ln(const float* __restrict__ x1, const float* __restrict__ x2,
                       const float* __restrict__ g, const float* __restrict__ bb,
                       float* __restrict__ out, float* __restrict__ out_r) {
    const int row = blockIdx.x;
    const int tid = threadIdx.x;
    __shared__ float red[256];
    __shared__ float red2[256];
    const float* a = x1 + (size_t)row * DMODEL;
    const float* c = x2 + (size_t)row * DMODEL;
    float v0 = a[tid] + c[tid];
    float v1 = a[tid + 256] + c[tid + 256];
    red[tid] = v0 + v1;
    red2[tid] = v0 * v0 + v1 * v1;
    __syncthreads();
    for (int o = 128; o > 0; o >>= 1) {
        if (tid < o) { red[tid] += red[tid + o]; red2[tid] += red2[tid + o]; }
        __syncthreads();
    }
    const float mu = red[0] * (1.0f / DMODEL);
    const float var = red2[0] * (1.0f / DMODEL) - mu * mu;
    const float rstd = rsqrtf(var + 1e-5f);
    float* o = out + (size_t)row * DMODEL;
    float r0 = (v0 - mu) * rstd * g[tid] + bb[tid];
    float r1 = (v1 - mu) * rstd * g[tid + 256] + bb[tid + 256];
    o[tid] = r0;
    o[tid + 256] = r1;
    if (out_r) {
        float* orr = out_r + (size_t)row * DMODEL;
        orr[tid] = f2tf(r0);
        orr[tid + 256] = f2tf(r1);
    }
}

// ---------------- launch ----------------
extern "C" void kernel_launch(void* const* d_in, const int* in_sizes, int n_in,
                              void* d_out, int out_size) {
    const float* inputs = (const float*)d_in[0];
    const float* r      = (const float*)d_in[1];
    const float* u      = (const float*)d_in[2];
    const float* v      = (const float*)d_in[3];
    const float* mem    = (const float*)d_in[4];
    const float* Wqkv   = (const float*)d_in[6];
    const float* Wr     = (const float*)d_in[7];
    const float* Wo     = (const float*)d_in[8];
    const float* ln1_g  = (const float*)d_in[9];
    const float* ln1_b  = (const float*)d_in[10];
    const float* w1     = (const float*)d_in[11];
    const float* b1     = (const float*)d_in[12];
    const float* w2     = (const float*)d_in[13];
    const float* b2     = (const float*)d_in[14];
    const float* ln2_g  = (const float*)d_in[15];
    const float* ln2_b  = (const float*)d_in[16];

    static bool attr_done = false;
    if (!attr_done) {
        cudaFuncSetAttribute(lin_gemm, cudaFuncAttributeMaxDynamicSharedMemorySize, SMEM_DYN);
        cudaFuncSetAttribute(score_bd, cudaFuncAttributeMaxDynamicSharedMemorySize, SMEM_DYN);
        cudaFuncSetAttribute(score_ac, cudaFuncAttributeMaxDynamicSharedMemorySize, SMEM_DYN);
        attr_done = true;
    }

    float *qkvp, *rkp, *qup, *qvp, *vtp, *sp, *bdp, *attnp, *aop, *yp, *yrp, *hp, *zp, *rnd;
    float2 *statp, *partp;
    cudaGetSymbolAddress((void**)&qkvp,  g_qkv);
    cudaGetSymbolAddress((void**)&rkp,   g_rk);
    cudaGetSymbolAddress((void**)&qup,   g_qu);
    cudaGetSymbolAddress((void**)&qvp,   g_qv);
    cudaGetSymbolAddress((void**)&vtp,   g_vt);
    cudaGetSymbolAddress((void**)&sp,    g_S);
    cudaGetSymbolAddress((void**)&bdp,   g_BD);
    cudaGetSymbolAddress((void**)&statp, g_stat);
    cudaGetSymbolAddress((void**)&partp, g_part);
    cudaGetSymbolAddress((void**)&attnp, g_attn);
    cudaGetSymbolAddress((void**)&aop,   g_ao);
    cudaGetSymbolAddress((void**)&yp,    g_y);
    cudaGetSymbolAddress((void**)&yrp,   g_yr);
    cudaGetSymbolAddress((void**)&hp,    g_h);
    cudaGetSymbolAddress((void**)&zp,    g_z);
    cudaGetSymbolAddress((void**)&rnd,   g_rnd);

    const float* memr  = rnd + OFF_MEM;
    const float* rr    = rnd + OFF_R;
    const float* wqkvr = rnd + OFF_WQKV;
    const float* wrr   = rnd + OFF_WR;
    const float* wor   = rnd + OFF_WO;
    const float* w1r   = rnd + OFF_W1;
    const float* w2r   = rnd + OFF_W2;

    // 1: fused RNA rounding
    round_all<<<(2162688 + 255) / 256, 256>>>(mem, inputs, r, Wqkv, Wr, Wo, w1, w2,
                                              (float4*)rnd);
    // 2: qkv projection, single GEMM over concat(mem, inputs) = rnd[0:8192*512]
    lin_gemm<<<dim3(QKVW / 128, KROWS / 128), 128, SMEM_DYN>>>(memr, wqkvr, nullptr, qkvp,
                                                               DMODEL, QKVW, 4);
    // 3: rk projection
    lin_gemm<<<dim3(DMODEL / 128, KLEN / 128), 128, SMEM_DYN>>>(rr, wrr, nullptr, rkp,
                                                                DMODEL, DMODEL, 4);
    // 4-5: prep
    prep_quv<<<dim3(QLEN, BATCH), 512>>>(qkvp, u, v, qup, qvp);
    prep_vt<<<dim3(KLEN / 32, DHEAD / 32, BH), 256>>>(qkvp, vtp);
    // 6: score_bd (profiled launch)
    score_bd<<<dim3(KLEN / 128, QLEN / 128, BH), 128, SMEM_DYN>>>(qvp, rkp, bdp);
    // 7-9
    score_ac<<<dim3(KLEN / 128, QLEN / 128, BH), 128, SMEM_DYN>>>(qup, qkvp, bdp, sp, partp);
    statcombine<<<(BH * QLEN + 255) / 256, 256>>>(partp, statp);
    float* prob_out = (float*)d_out + QLEN * BATCH * DMODEL;
    probout<<<dim3(KLEN / 32, QLEN), 256>>>(sp, statp, prob_out);
    // 10-15
    attn_exp_gemm<<<dim3(QLEN / 128, BH), 128>>>(sp, statp, vtp, attnp);
    lin_gemm<<<dim3(DMODEL / 128, QROWS / 128), 128, SMEM_DYN>>>(attnp, wor, nullptr, aop,
                                                                 DMODEL, DMODEL, 0);
    add_ln<<<QROWS, 256>>>(inputs, aop, ln1_g, ln1_b, yp, yrp);
    lin_gemm<<<dim3(DMLP / 128, QROWS / 128), 128, SMEM_DYN>>>(yrp, w1r, b1, hp,
                                                               DMODEL, DMLP, 7);
    lin_gemm<<<dim3(DMODEL / 128, QROWS / 128), 128, SMEM_DYN>>>(hp, w2r, b2, zp,
                                                                 DMLP, DMODEL, 1);
    add_ln<<<QROWS, 256>>>(yp, zp, ln2_g, ln2_b, (float*)d_out, nullptr);
}